// round 5
// baseline (speedup 1.0000x reference)
#include <cuda_runtime.h>
#include <math.h>

// ---------------------------------------------------------------------------
// GatedDeltaNet encoder block, fp32 baseline.
// B=4, T=1024, D=1024, H=16, DK=DV=64, K_conv=4, I=2816
// out[0 .. 4194304)           = final hidden  [B,T,D]
// out[4194304 .. 4456448)     = last_state    [B,H,DK,DV]
// ---------------------------------------------------------------------------

#define B_    4
#define T_    1024
#define D_    1024
#define H_    16
#define DK_   64
#define DV_   64
#define ROWS  (B_ * T_)          // 4096
#define I_    2816
#define TWOI  (2 * I_)           // 5632

static constexpr size_t SZ       = (size_t)ROWS * D_;        // 4194304
static constexpr size_t OFF_H    = 0 * SZ;
static constexpr size_t OFF_QPRE = 1 * SZ;
static constexpr size_t OFF_KPRE = 2 * SZ;
static constexpr size_t OFF_VPRE = 3 * SZ;
static constexpr size_t OFF_Q    = 4 * SZ;
static constexpr size_t OFF_K    = 5 * SZ;
static constexpr size_t OFF_V    = 6 * SZ;
static constexpr size_t OFF_O    = 7 * SZ;
static constexpr size_t OFF_H2   = 8 * SZ;
static constexpr size_t OFF_H3   = 9 * SZ;
static constexpr size_t OFF_GY   = 10 * SZ;                          // 4096*5632
static constexpr size_t OFF_U    = OFF_GY + (size_t)ROWS * TWOI;     // 4096*2816
static constexpr size_t OFF_BETA = OFF_U + (size_t)ROWS * I_;
static constexpr size_t OFF_G    = OFF_BETA + (size_t)ROWS * H_;
static constexpr size_t POOL_SZ  = OFF_G + (size_t)ROWS * H_;        // 76,677,120 floats

static __device__ float g_pool[POOL_SZ];

// ---------------------------------------------------------------------------
// RMSNorm over D=1024 per row. 1 block / row, 256 threads, float4.
// ---------------------------------------------------------------------------
__global__ void __launch_bounds__(256) rmsnorm_row_kernel(
    const float* __restrict__ x, const float* __restrict__ w,
    float* __restrict__ y) {
  int row = blockIdx.x;
  int tid = threadIdx.x;
  const float4* xr = reinterpret_cast<const float4*>(x + (size_t)row * D_);
  float4 v = xr[tid];
  float ss = v.x * v.x + v.y * v.y + v.z * v.z + v.w * v.w;
#pragma unroll
  for (int o = 16; o > 0; o >>= 1) ss += __shfl_xor_sync(0xffffffffu, ss, o);
  __shared__ float red[8];
  if ((tid & 31) == 0) red[tid >> 5] = ss;
  __syncthreads();
  float tot = red[0] + red[1] + red[2] + red[3] + red[4] + red[5] + red[6] + red[7];
  float r = rsqrtf(tot * (1.0f / 1024.0f) + 1e-6f);
  float4 wv = reinterpret_cast<const float4*>(w)[tid];
  float4 ov = make_float4(v.x * r * wv.x, v.y * r * wv.y,
                          v.z * r * wv.z, v.w * r * wv.w);
  reinterpret_cast<float4*>(y + (size_t)row * D_)[tid] = ov;
}

// ---------------------------------------------------------------------------
// SGEMM: C[M,N] = A[M,K] @ B[K,N] (+ Res). 128x128 tile, BK=8, 8x8 microtile.
// M%128==0, N%128==0, K%8==0 (true for all calls here).
// ---------------------------------------------------------------------------
__global__ void __launch_bounds__(256) sgemm_kernel(
    const float* __restrict__ A, const float* __restrict__ B,
    const float* __restrict__ Res, float* __restrict__ C,
    int M, int N, int K) {
  __shared__ float As[8][128];
  __shared__ float Bs[8][128];
  int tid = threadIdx.x;
  int bm = blockIdx.y * 128;
  int bn = blockIdx.x * 128;
  int tx = tid & 15;
  int ty = tid >> 4;
  int arow = tid >> 1;
  int acol = (tid & 1) << 2;
  int brow = tid >> 5;
  int bcol = (tid & 31) << 2;
  const float* Ap = A + (size_t)(bm + arow) * K + acol;
  const float* Bp = B + (size_t)brow * N + bn + bcol;
  float acc[8][8];
#pragma unroll
  for (int i = 0; i < 8; i++)
#pragma unroll
    for (int j = 0; j < 8; j++) acc[i][j] = 0.f;

  for (int k0 = 0; k0 < K; k0 += 8) {
    float4 av = *reinterpret_cast<const float4*>(Ap);
    float4 bv = *reinterpret_cast<const float4*>(Bp);
    As[acol + 0][arow] = av.x;
    As[acol + 1][arow] = av.y;
    As[acol + 2][arow] = av.z;
    As[acol + 3][arow] = av.w;
    *reinterpret_cast<float4*>(&Bs[brow][bcol]) = bv;
    __syncthreads();
#pragma unroll
    for (int kk = 0; kk < 8; kk++) {
      float4 a0 = *reinterpret_cast<const float4*>(&As[kk][ty * 8]);
      float4 a1 = *reinterpret_cast<const float4*>(&As[kk][ty * 8 + 4]);
      float4 b0 = *reinterpret_cast<const float4*>(&Bs[kk][tx * 8]);
      float4 b1 = *reinterpret_cast<const float4*>(&Bs[kk][tx * 8 + 4]);
      float a[8] = {a0.x, a0.y, a0.z, a0.w, a1.x, a1.y, a1.z, a1.w};
      float b[8] = {b0.x, b0.y, b0.z, b0.w, b1.x, b1.y, b1.z, b1.w};
#pragma unroll
      for (int i = 0; i < 8; i++)
#pragma unroll
        for (int j = 0; j < 8; j++) acc[i][j] += a[i] * b[j];
    }
    __syncthreads();
    Ap += 8;
    Bp += (size_t)8 * N;
  }

#pragma unroll
  for (int i = 0; i < 8; i++) {
    size_t crow = (size_t)(bm + ty * 8 + i) * N + bn + tx * 8;
    if (Res != nullptr) {
#pragma unroll
      for (int j = 0; j < 8; j++) C[crow + j] = acc[i][j] + Res[crow + j];
    } else {
#pragma unroll
      for (int j = 0; j < 8; j++) C[crow + j] = acc[i][j];
    }
  }
}

// ---------------------------------------------------------------------------
// Causal depthwise conv1d (K=4, zero left-pad) + SiLU. Layout [B,T,C=1024].
// ---------------------------------------------------------------------------
__global__ void __launch_bounds__(256) conv_silu_kernel(
    const float* __restrict__ x, const float* __restrict__ w,
    float* __restrict__ y) {
  int idx = blockIdx.x * 256 + threadIdx.x;
  if (idx >= ROWS * D_) return;
  int c = idx & 1023;
  int t = (idx >> 10) & 1023;
  float acc = 0.f;
#pragma unroll
  for (int i = 0; i < 4; i++) {
    int tt = t + i - 3;
    if (tt >= 0) acc += x[idx + (i - 3) * 1024] * w[c * 4 + i];
  }
  y[idx] = acc / (1.f + expf(-acc));  // silu
}

// ---------------------------------------------------------------------------
// Per-64-group norm, 1 warp / group, in place.
//  rms_mode=0: x * rsqrt(sum(x^2)+eps) * scale            (l2norm)
//  rms_mode=1: x * rsqrt(mean(x^2)+eps) * w[pos]          (head RMSNorm)
// ---------------------------------------------------------------------------
__global__ void __launch_bounds__(256) norm64_kernel(
    float* __restrict__ x, const float* __restrict__ w,
    float scale, int rms_mode, int ngroups) {
  int gw = (blockIdx.x * blockDim.x + threadIdx.x) >> 5;
  int lane = threadIdx.x & 31;
  if (gw >= ngroups) return;
  float* p = x + (size_t)gw * 64;
  float a = p[lane];
  float b = p[lane + 32];
  float ss = a * a + b * b;
#pragma unroll
  for (int o = 16; o > 0; o >>= 1) ss += __shfl_xor_sync(0xffffffffu, ss, o);
  float r;
  if (rms_mode) {
    r = rsqrtf(ss * (1.f / 64.f) + 1e-6f);
    a *= w[lane];
    b *= w[lane + 32];
  } else {
    r = rsqrtf(ss + 1e-6f) * scale;
  }
  p[lane] = a * r;
  p[lane + 32] = b * r;
}

// ---------------------------------------------------------------------------
// beta = 2*sigmoid(h@Wb); g = -exp(A_log)*softplus(h@Wa + dt_bias)
// One thread per (row, head). Wb/Wa are [1024,16].
// ---------------------------------------------------------------------------
__global__ void __launch_bounds__(256) betag_kernel(
    const float* __restrict__ h, const float* __restrict__ Wb,
    const float* __restrict__ Wa, const float* __restrict__ dt_bias,
    const float* __restrict__ A_log, float* __restrict__ beta,
    float* __restrict__ gout) {
  int idx = blockIdx.x * 256 + threadIdx.x;
  if (idx >= ROWS * H_) return;
  int hh = idx & 15;
  int row = idx >> 4;
  const float* hr = h + (size_t)row * D_;
  float sb = 0.f, sa = 0.f;
  for (int k = 0; k < D_; k++) {
    float hv = hr[k];
    sb += hv * Wb[k * 16 + hh];
    sa += hv * Wa[k * 16 + hh];
  }
  beta[idx] = 2.f / (1.f + expf(-sb));
  float z = sa + dt_bias[hh];
  float sp = (z > 20.f) ? z : log1pf(expf(z));
  gout[idx] = -expf(A_log[hh]) * sp;
}

// ---------------------------------------------------------------------------
// Sequential gated delta-rule scan. grid = B*H blocks, 256 threads.
// Thread (col = tid>>2, kq = tid&3) owns S[kq*16 .. kq*16+15][col] in regs.
// q/k/v layout [B,T,H*64]; beta/g layout [B,T,H].
// Writes o [B,T,H*64] and final state [B,H,64,64].
// ---------------------------------------------------------------------------
__global__ void __launch_bounds__(256) scan_kernel(
    const float* __restrict__ q, const float* __restrict__ k,
    const float* __restrict__ v, const float* __restrict__ beta,
    const float* __restrict__ g, float* __restrict__ o,
    float* __restrict__ state_out) {
  int bh = blockIdx.x;          // 0..63
  int b  = bh >> 4;
  int h  = bh & 15;
  int tid = threadIdx.x;
  int col = tid >> 2;           // 0..63  (v-column)
  int kq  = tid & 3;            // k-quarter

  __shared__ float qs[64], ks[64], vs[64], sc[2];
  float s[16];
#pragma unroll
  for (int i = 0; i < 16; i++) s[i] = 0.f;

  size_t vecbase = (size_t)b * T_ * 1024 + (size_t)h * 64;
  int bgbase = b * T_ * H_ + h;

  for (int t = 0; t < T_; t++) {
    size_t off = vecbase + (size_t)t * 1024;
    if (tid < 64)        qs[tid]        = q[off + tid];
    else if (tid < 128)  ks[tid - 64]   = k[off + tid - 64];
    else if (tid < 192)  vs[tid - 128]  = v[off + tid - 128];
    else if (tid == 192) sc[0] = beta[bgbase + t * H_];
    else if (tid == 193) sc[1] = g[bgbase + t * H_];
    __syncthreads();

    float eg = expf(sc[1]);
    float bt = sc[0];

    float kv = 0.f;
#pragma unroll
    for (int i = 0; i < 16; i++) {
      s[i] *= eg;
      kv += ks[kq * 16 + i] * s[i];
    }
    kv += __shfl_xor_sync(0xffffffffu, kv, 1);
    kv += __shfl_xor_sync(0xffffffffu, kv, 2);

    float delta = (vs[col] - kv) * bt;

    float op = 0.f;
#pragma unroll
    for (int i = 0; i < 16; i++) {
      float kk = ks[kq * 16 + i];
      s[i] += kk * delta;
      op += qs[kq * 16 + i] * s[i];
    }
    op += __shfl_xor_sync(0xffffffffu, op, 1);
    op += __shfl_xor_sync(0xffffffffu, op, 2);
    if (kq == 0) o[off + col] = op;
    __syncthreads();
  }

  // last_state [B,H,DK,DV]: S[k][v] at ((bh*64)+k)*64 + v
  float* sp = state_out + (size_t)bh * 64 * 64;
#pragma unroll
  for (int i = 0; i < 16; i++) sp[(kq * 16 + i) * 64 + col] = s[i];
}

// ---------------------------------------------------------------------------
// SwiGLU: u[row,col] = silu(gy[row,col]) * gy[row,col+I]
// ---------------------------------------------------------------------------
__global__ void __launch_bounds__(256) swiglu_kernel(
    const float* __restrict__ gy, float* __restrict__ u) {
  int idx = blockIdx.x * 256 + threadIdx.x;
  if (idx >= ROWS * I_) return;
  int row = idx / I_;
  int col = idx - row * I_;
  float gv = gy[(size_t)row * TWOI + col];
  float yv = gy[(size_t)row * TWOI + I_ + col];
  u[idx] = gv / (1.f + expf(-gv)) * yv;
}

// ---------------------------------------------------------------------------
extern "C" void kernel_launch(void* const* d_in, const int* in_sizes, int n_in,
                              void* d_out, int out_size) {
  const float* x           = (const float*)d_in[0];
  const float* attn_norm_w = (const float*)d_in[1];
  const float* Wq          = (const float*)d_in[2];
  const float* Wk          = (const float*)d_in[3];
  const float* Wv          = (const float*)d_in[4];
  const float* conv_q_w    = (const float*)d_in[5];
  const float* conv_k_w    = (const float*)d_in[6];
  const float* conv_v_w    = (const float*)d_in[7];
  const float* Wb          = (const float*)d_in[8];
  const float* Wa          = (const float*)d_in[9];
  const float* dt_bias     = (const float*)d_in[10];
  const float* A_log       = (const float*)d_in[11];
  const float* o_norm_w    = (const float*)d_in[12];
  const float* Wo          = (const float*)d_in[13];
  const float* mlp_norm_w  = (const float*)d_in[14];
  const float* Wg          = (const float*)d_in[15];
  const float* Wd          = (const float*)d_in[16];
  float* out = (float*)d_out;

  float* pool = nullptr;
  cudaGetSymbolAddress((void**)&pool, g_pool);

  float* hbuf = pool + OFF_H;
  float* qpre = pool + OFF_QPRE;
  float* kpre = pool + OFF_KPRE;
  float* vpre = pool + OFF_VPRE;
  float* qbuf = pool + OFF_Q;
  float* kbuf = pool + OFF_K;
  float* vbuf = pool + OFF_V;
  float* obuf = pool + OFF_O;
  float* h2   = pool + OFF_H2;
  float* h3   = pool + OFF_H3;
  float* gy   = pool + OFF_GY;
  float* ubuf = pool + OFF_U;
  float* bbuf = pool + OFF_BETA;
  float* gbuf = pool + OFF_G;

  // 1. h = rmsnorm(x, attn_norm_w)
  rmsnorm_row_kernel<<<ROWS, 256>>>(x, attn_norm_w, hbuf);

  // 2. q/k/v projections
  dim3 gSq(D_ / 128, ROWS / 128);  // (8, 32)
  sgemm_kernel<<<gSq, 256>>>(hbuf, Wq, nullptr, qpre, ROWS, D_, D_);
  sgemm_kernel<<<gSq, 256>>>(hbuf, Wk, nullptr, kpre, ROWS, D_, D_);
  sgemm_kernel<<<gSq, 256>>>(hbuf, Wv, nullptr, vpre, ROWS, D_, D_);

  // 3. beta / g gates
  betag_kernel<<<(ROWS * H_) / 256, 256>>>(hbuf, Wb, Wa, dt_bias, A_log,
                                           bbuf, gbuf);

  // 4. causal depthwise conv + SiLU
  int nel = ROWS * D_;
  conv_silu_kernel<<<nel / 256, 256>>>(qpre, conv_q_w, qbuf);
  conv_silu_kernel<<<nel / 256, 256>>>(kpre, conv_k_w, kbuf);
  conv_silu_kernel<<<nel / 256, 256>>>(vpre, conv_v_w, vbuf);

  // 5. l2norm per head; q also scaled by DK^-0.5
  int ngrp = ROWS * H_;
  int nblk64 = (ngrp * 32) / 256;
  norm64_kernel<<<nblk64, 256>>>(qbuf, nullptr, 0.125f, 0, ngrp);
  norm64_kernel<<<nblk64, 256>>>(kbuf, nullptr, 1.0f, 0, ngrp);

  // 6. gated delta-rule scan (writes o + last_state)
  scan_kernel<<<B_ * H_, 256>>>(qbuf, kbuf, vbuf, bbuf, gbuf, obuf, out + SZ);

  // 7. per-head output RMSNorm (in place)
  norm64_kernel<<<nblk64, 256>>>(obuf, o_norm_w, 1.0f, 1, ngrp);

  // 8. attn_out = o @ Wo + x  -> h2
  sgemm_kernel<<<gSq, 256>>>(obuf, Wo, x, h2, ROWS, D_, D_);

  // 9. h3 = rmsnorm(h2, mlp_norm_w)
  rmsnorm_row_kernel<<<ROWS, 256>>>(h2, mlp_norm_w, h3);

  // 10. gy = h3 @ Wg   [4096, 5632]
  dim3 gSg(TWOI / 128, ROWS / 128);  // (44, 32)
  sgemm_kernel<<<gSg, 256>>>(h3, Wg, nullptr, gy, ROWS, TWOI, D_);

  // 11. u = silu(gate) * y
  swiglu_kernel<<<(ROWS * I_) / 256, 256>>>(gy, ubuf);

  // 12. out = u @ Wd + h2
  sgemm_kernel<<<gSq, 256>>>(ubuf, Wd, h2, out, ROWS, D_, I_);
}

// round 8
// speedup vs baseline: 1.5188x; 1.5188x over previous
#include <cuda_runtime.h>
#include <cuda_bf16.h>
#include <math.h>
#include <stdint.h>

// ---------------------------------------------------------------------------
// GatedDeltaNet encoder block. HMMA (mma.sync bf16, hi/lo split) GEMMs.
// B=4, T=1024, D=1024, H=16, DK=DV=64, K_conv=4, I=2816
// out[0..4194304) = final hidden [B,T,D]; out[4194304..] = last_state
// ---------------------------------------------------------------------------

#define B_    4
#define T_    1024
#define D_    1024
#define H_    16
#define ROWS  (B_ * T_)          // 4096
#define I_    2816
#define TWOI  (2 * I_)           // 5632

static constexpr size_t SZ       = (size_t)ROWS * D_;        // 4194304
static constexpr size_t OFF_H    = 0 * SZ;
static constexpr size_t OFF_QPRE = 1 * SZ;
static constexpr size_t OFF_KPRE = 2 * SZ;
static constexpr size_t OFF_VPRE = 3 * SZ;
static constexpr size_t OFF_Q    = 4 * SZ;
static constexpr size_t OFF_K    = 5 * SZ;
static constexpr size_t OFF_V    = 6 * SZ;
static constexpr size_t OFF_O    = 7 * SZ;
static constexpr size_t OFF_H2   = 8 * SZ;
static constexpr size_t OFF_H3   = 9 * SZ;
static constexpr size_t OFF_GY   = 10 * SZ;
static constexpr size_t OFF_U    = OFF_GY + (size_t)ROWS * TWOI;
static constexpr size_t OFF_BETA = OFF_U + (size_t)ROWS * I_;
static constexpr size_t OFF_G    = OFF_BETA + (size_t)ROWS * H_;
static constexpr size_t POOL_SZ  = OFF_G + (size_t)ROWS * H_;

static __device__ float g_pool[POOL_SZ];

// bf16 scratch pool -------------------------------------------------------
static constexpr size_t S1  = (size_t)ROWS * D_;      // 4194304
static constexpr size_t S2  = (size_t)ROWS * I_;      // 11534336
static constexpr size_t W1  = (size_t)D_ * D_;        // 1048576
static constexpr size_t SWG = (size_t)TWOI * D_;      // 5767168  (Wg^T)
static constexpr size_t SWD = (size_t)D_ * I_;        // 2883584  (Wd^T)

static constexpr size_t BF_AH  = 0;
static constexpr size_t BF_AL  = 1 * S1;
static constexpr size_t BF_OH  = 2 * S1;
static constexpr size_t BF_OL  = 3 * S1;
static constexpr size_t BF_3H  = 4 * S1;
static constexpr size_t BF_3L  = 5 * S1;
static constexpr size_t BF_UH  = 6 * S1;
static constexpr size_t BF_UL  = 6 * S1 + S2;
static constexpr size_t BF_WQ  = 6 * S1 + 2 * S2;     // hi, then lo at +W1
static constexpr size_t BF_WK  = BF_WQ + 2 * W1;
static constexpr size_t BF_WV  = BF_WK + 2 * W1;
static constexpr size_t BF_WO  = BF_WV + 2 * W1;
static constexpr size_t BF_WG  = BF_WO + 2 * W1;      // hi, lo at +SWG
static constexpr size_t BF_WD  = BF_WG + 2 * SWG;     // hi, lo at +SWD
static constexpr size_t BF_SZ  = BF_WD + 2 * SWD;

static __device__ __nv_bfloat16 g_bf[BF_SZ];

// ---------------------------------------------------------------------------
// helpers
// ---------------------------------------------------------------------------
__device__ __forceinline__ uint32_t smem_u32(const void* p) {
  uint32_t r;
  asm("{ .reg .u64 t; cvta.to.shared.u64 t, %1; cvt.u32.u64 %0, t; }"
      : "=r"(r) : "l"(p));
  return r;
}

__device__ __forceinline__ uint32_t lds32(uint32_t a) {
  uint32_t v;
  asm volatile("ld.shared.b32 %0, [%1];" : "=r"(v) : "r"(a));
  return v;
}

__device__ __forceinline__ void cp16(uint32_t dst, const void* src) {
  asm volatile("cp.async.cg.shared.global [%0], [%1], 16;"
               :: "r"(dst), "l"(src));
}

__device__ __forceinline__ void mma16816(float* d, const uint32_t* a,
                                         const uint32_t* b) {
  asm volatile(
      "mma.sync.aligned.m16n8k16.row.col.f32.bf16.bf16.f32 "
      "{%0,%1,%2,%3}, {%4,%5,%6,%7}, {%8,%9}, {%0,%1,%2,%3};"
      : "+f"(d[0]), "+f"(d[1]), "+f"(d[2]), "+f"(d[3])
      : "r"(a[0]), "r"(a[1]), "r"(a[2]), "r"(a[3]), "r"(b[0]), "r"(b[1]));
}

// ---------------------------------------------------------------------------
// HMMA bf16 GEMM: C[M,N] = (Ah+Al)[M,K] @ (Bh+Bl)^T  (+ Res)
// A: [M,K] bf16 row-major (hi/lo). B: [N,K] bf16 row-major (hi/lo).
// Tile 128x128, BK=32, 3-stage cp.async. 256 threads (8 warps, 2x4),
// warp tile 64x32 via mma.m16n8k16 (4 m-tiles x 4 n-tiles x 2 k-steps x 3).
// smem rows padded to 80B (32 bf16 data + 8 pad) -> conflict-free LDS.
// ---------------------------------------------------------------------------
static constexpr int TILE_B   = 10240;         // 128 rows * 80 B
static constexpr int STAGE_B  = 4 * TILE_B;    // Ah, Al, Bh, Bl
static constexpr int GEMM_SMEM = 3 * STAGE_B;  // 122880

__device__ __forceinline__ void load_stage(
    const __nv_bfloat16* __restrict__ Ah, const __nv_bfloat16* __restrict__ Al,
    const __nv_bfloat16* __restrict__ Bh, const __nv_bfloat16* __restrict__ Bl,
    int K, int m0, int n0, int k0, uint32_t sb, int stage, int tid) {
  uint32_t sdst = sb + stage * STAGE_B;
#pragma unroll
  for (int t = 0; t < 8; t++) {
    int idx = t * 256 + tid;        // 0..2047
    int tile = idx >> 9;            // 0..3
    int row = (idx >> 2) & 127;
    int ch = idx & 3;
    const __nv_bfloat16* base;
    int row0;
    if (tile == 0)      { base = Ah; row0 = m0; }
    else if (tile == 1) { base = Al; row0 = m0; }
    else if (tile == 2) { base = Bh; row0 = n0; }
    else                { base = Bl; row0 = n0; }
    const void* src = base + (size_t)(row0 + row) * K + k0 + ch * 8;
    cp16(sdst + tile * TILE_B + row * 80 + ch * 16, src);
  }
}

__global__ void __launch_bounds__(256, 1)
bf16gemm_kernel(const __nv_bfloat16* __restrict__ Ah,
                const __nv_bfloat16* __restrict__ Al,
                const __nv_bfloat16* __restrict__ Bh,
                const __nv_bfloat16* __restrict__ Bl,
                const float* __restrict__ Res, float* __restrict__ C,
                int M, int N, int K) {
  extern __shared__ char sm[];
  uint32_t sb = smem_u32(sm);
  const int tid = threadIdx.x;
  const int wid = tid >> 5;
  const int lid = tid & 31;
  const int gid = lid >> 2;   // 0..7
  const int tig = lid & 3;    // 0..3
  const int wm = wid >> 2;    // 0..1
  const int wn = wid & 3;     // 0..3
  const int m0 = blockIdx.y * 128;
  const int n0 = blockIdx.x * 128;
  const int nc = K >> 5;

  float acc[4][4][4];
#pragma unroll
  for (int i = 0; i < 4; i++)
#pragma unroll
    for (int j = 0; j < 4; j++)
#pragma unroll
      for (int r = 0; r < 4; r++) acc[i][j][r] = 0.f;

  // prologue: stages 0,1
  load_stage(Ah, Al, Bh, Bl, K, m0, n0, 0, sb, 0, tid);
  asm volatile("cp.async.commit_group;");
  load_stage(Ah, Al, Bh, Bl, K, m0, n0, 32, sb, 1, tid);
  asm volatile("cp.async.commit_group;");

  for (int c = 0; c < nc; c++) {
    asm volatile("cp.async.wait_group 1;");
    __syncthreads();
    if (c + 2 < nc)
      load_stage(Ah, Al, Bh, Bl, K, m0, n0, (c + 2) * 32, sb, (c + 2) % 3, tid);
    asm volatile("cp.async.commit_group;");

    uint32_t st = sb + (c % 3) * STAGE_B;
    uint32_t aBase = st + (uint32_t)(wm * 64) * 80;
    uint32_t bBase = st + 2 * TILE_B + (uint32_t)(wn * 32) * 80;
#pragma unroll
    for (int ks = 0; ks < 2; ks++) {
      int kb = ks * 16;
      uint32_t ah[4][4], al[4][4], bh[4][2], bl[4][2];
#pragma unroll
      for (int mi = 0; mi < 4; mi++) {
#pragma unroll
        for (int r = 0; r < 4; r++) {
          int row = mi * 16 + gid + (r & 1) * 8;
          int col = kb + tig * 2 + (r >> 1) * 8;
          uint32_t ad = aBase + row * 80 + col * 2;
          ah[mi][r] = lds32(ad);
          al[mi][r] = lds32(ad + TILE_B);
        }
      }
#pragma unroll
      for (int ni = 0; ni < 4; ni++) {
#pragma unroll
        for (int r = 0; r < 2; r++) {
          int n = ni * 8 + gid;
          int kk = kb + tig * 2 + r * 8;
          uint32_t bd = bBase + n * 80 + kk * 2;
          bh[ni][r] = lds32(bd);
          bl[ni][r] = lds32(bd + TILE_B);
        }
      }
#pragma unroll
      for (int mi = 0; mi < 4; mi++)
#pragma unroll
        for (int ni = 0; ni < 4; ni++) {
          mma16816(acc[mi][ni], ah[mi], bh[ni]);
          mma16816(acc[mi][ni], ah[mi], bl[ni]);
          mma16816(acc[mi][ni], al[mi], bh[ni]);
        }
    }
    __syncthreads();
  }

  // epilogue
  const int mrow = m0 + wm * 64;
  const int ncol = n0 + wn * 32;
#pragma unroll
  for (int mi = 0; mi < 4; mi++) {
#pragma unroll
    for (int ni = 0; ni < 4; ni++) {
      int r0 = mrow + mi * 16 + gid;
      int cc = ncol + ni * 8 + tig * 2;
      float2 v0 = make_float2(acc[mi][ni][0], acc[mi][ni][1]);
      float2 v1 = make_float2(acc[mi][ni][2], acc[mi][ni][3]);
      if (Res != nullptr) {
        float2 r0v = *reinterpret_cast<const float2*>(Res + (size_t)r0 * N + cc);
        float2 r1v = *reinterpret_cast<const float2*>(Res + (size_t)(r0 + 8) * N + cc);
        v0.x += r0v.x; v0.y += r0v.y;
        v1.x += r1v.x; v1.y += r1v.y;
      }
      *reinterpret_cast<float2*>(C + (size_t)r0 * N + cc) = v0;
      *reinterpret_cast<float2*>(C + (size_t)(r0 + 8) * N + cc) = v1;
    }
  }
}

// ---------------------------------------------------------------------------
// Elementwise split: fp32 -> (hi, lo) bf16, same layout.
// ---------------------------------------------------------------------------
__global__ void __launch_bounds__(256) split_kernel(
    const float* __restrict__ x, __nv_bfloat16* __restrict__ hi,
    __nv_bfloat16* __restrict__ lo, int n4) {
  int i = blockIdx.x * 256 + threadIdx.x;
  if (i >= n4) return;
  float4 v = reinterpret_cast<const float4*>(x)[i];
  __nv_bfloat16 h0 = __float2bfloat16_rn(v.x);
  __nv_bfloat16 h1 = __float2bfloat16_rn(v.y);
  __nv_bfloat16 h2 = __float2bfloat16_rn(v.z);
  __nv_bfloat16 h3 = __float2bfloat16_rn(v.w);
  __nv_bfloat16 l0 = __float2bfloat16_rn(v.x - __bfloat162float(h0));
  __nv_bfloat16 l1 = __float2bfloat16_rn(v.y - __bfloat162float(h1));
  __nv_bfloat16 l2 = __float2bfloat16_rn(v.z - __bfloat162float(h2));
  __nv_bfloat16 l3 = __float2bfloat16_rn(v.w - __bfloat162float(h3));
  reinterpret_cast<__nv_bfloat162*>(hi)[2 * i + 0] = __nv_bfloat162(h0, h1);
  reinterpret_cast<__nv_bfloat162*>(hi)[2 * i + 1] = __nv_bfloat162(h2, h3);
  reinterpret_cast<__nv_bfloat162*>(lo)[2 * i + 0] = __nv_bfloat162(l0, l1);
  reinterpret_cast<__nv_bfloat162*>(lo)[2 * i + 1] = __nv_bfloat162(l2, l3);
}

// ---------------------------------------------------------------------------
// Weight transpose + split: W[K,N] fp32 -> Th/Tl[N,K] bf16.
// ---------------------------------------------------------------------------
__global__ void __launch_bounds__(256) wsplit_kernel(
    const float* __restrict__ W, __nv_bfloat16* __restrict__ Th,
    __nv_bfloat16* __restrict__ Tl, int K, int N) {
  __shared__ float t[32][33];
  int n0 = blockIdx.x * 32, k0 = blockIdx.y * 32;
  int tx = threadIdx.x & 31, ty = threadIdx.x >> 5;
  for (int i = ty; i < 32; i += 8)
    t[i][tx] = W[(size_t)(k0 + i) * N + n0 + tx];
  __syncthreads();
  for (int i = ty; i < 32; i += 8) {
    float v = t[tx][i];  // = W[k0+tx][n0+i]
    __nv_bfloat16 h = __float2bfloat16_rn(v);
    __nv_bfloat16 l = __float2bfloat16_rn(v - __bfloat162float(h));
    size_t o = (size_t)(n0 + i) * K + k0 + tx;
    Th[o] = h;
    Tl[o] = l;
  }
}

// ---------------------------------------------------------------------------
// RMSNorm over D=1024 per row.
// ---------------------------------------------------------------------------
__global__ void __launch_bounds__(256) rmsnorm_row_kernel(
    const float* __restrict__ x, const float* __restrict__ w,
    float* __restrict__ y) {
  int row = blockIdx.x;
  int tid = threadIdx.x;
  const float4* xr = reinterpret_cast<const float4*>(x + (size_t)row * D_);
  float4 v = xr[tid];
  float ss = v.x * v.x + v.y * v.y + v.z * v.z + v.w * v.w;
#pragma unroll
  for (int o = 16; o > 0; o >>= 1) ss += __shfl_xor_sync(0xffffffffu, ss, o);
  __shared__ float red[8];
  if ((tid & 31) == 0) red[tid >> 5] = ss;
  __syncthreads();
  float tot = red[0] + red[1] + red[2] + red[3] + red[4] + red[5] + red[6] + red[7];
  float r = rsqrtf(tot * (1.0f / 1024.0f) + 1e-6f);
  float4 wv = reinterpret_cast<const float4*>(w)[tid];
  float4 ov = make_float4(v.x * r * wv.x, v.y * r * wv.y,
                          v.z * r * wv.z, v.w * r * wv.w);
  reinterpret_cast<float4*>(y + (size_t)row * D_)[tid] = ov;
}

// ---------------------------------------------------------------------------
// Causal depthwise conv1d (K=4) + SiLU.
// ---------------------------------------------------------------------------
__global__ void __launch_bounds__(256) conv_silu_kernel(
    const float* __restrict__ x, const float* __restrict__ w,
    float* __restrict__ y) {
  int idx = blockIdx.x * 256 + threadIdx.x;
  if (idx >= ROWS * D_) return;
  int c = idx & 1023;
  int t = (idx >> 10) & 1023;
  float acc = 0.f;
#pragma unroll
  for (int i = 0; i < 4; i++) {
    int tt = t + i - 3;
    if (tt >= 0) acc += x[idx + (i - 3) * 1024] * w[c * 4 + i];
  }
  y[idx] = acc / (1.f + expf(-acc));
}

// ---------------------------------------------------------------------------
// Per-64-group norm, 1 warp / group, in place.
// ---------------------------------------------------------------------------
__global__ void __launch_bounds__(256) norm64_kernel(
    float* __restrict__ x, const float* __restrict__ w,
    float scale, int rms_mode, int ngroups) {
  int gw = (blockIdx.x * blockDim.x + threadIdx.x) >> 5;
  int lane = threadIdx.x & 31;
  if (gw >= ngroups) return;
  float* p = x + (size_t)gw * 64;
  float a = p[lane];
  float b = p[lane + 32];
  float ss = a * a + b * b;
#pragma unroll
  for (int o = 16; o > 0; o >>= 1) ss += __shfl_xor_sync(0xffffffffu, ss, o);
  float r;
  if (rms_mode) {
    r = rsqrtf(ss * (1.f / 64.f) + 1e-6f);
    a *= w[lane];
    b *= w[lane + 32];
  } else {
    r = rsqrtf(ss + 1e-6f) * scale;
  }
  p[lane] = a * r;
  p[lane + 32] = b * r;
}

// ---------------------------------------------------------------------------
// beta/g gates: warp per (row, head).
// ---------------------------------------------------------------------------
__global__ void __launch_bounds__(256) betag_kernel(
    const float* __restrict__ h, const float* __restrict__ Wb,
    const float* __restrict__ Wa, const float* __restrict__ dt_bias,
    const float* __restrict__ A_log, float* __restrict__ beta,
    float* __restrict__ gout) {
  int w = (blockIdx.x * 256 + threadIdx.x) >> 5;
  int lane = threadIdx.x & 31;
  if (w >= ROWS * H_) return;
  int row = w >> 4, hh = w & 15;
  const float* hr = h + (size_t)row * D_;
  float sb = 0.f, sa = 0.f;
  for (int k = lane; k < D_; k += 32) {
    float hv = hr[k];
    sb += hv * Wb[k * 16 + hh];
    sa += hv * Wa[k * 16 + hh];
  }
#pragma unroll
  for (int o = 16; o > 0; o >>= 1) {
    sb += __shfl_xor_sync(0xffffffffu, sb, o);
    sa += __shfl_xor_sync(0xffffffffu, sa, o);
  }
  if (lane == 0) {
    beta[w] = 2.f / (1.f + expf(-sb));
    float z = sa + dt_bias[hh];
    float sp = (z > 20.f) ? z : log1pf(expf(z));
    gout[w] = -expf(A_log[hh]) * sp;
  }
}

// ---------------------------------------------------------------------------
// Sequential gated delta-rule scan.
// ---------------------------------------------------------------------------
__global__ void __launch_bounds__(256) scan_kernel(
    const float* __restrict__ q, const float* __restrict__ k,
    const float* __restrict__ v, const float* __restrict__ beta,
    const float* __restrict__ g, float* __restrict__ o,
    float* __restrict__ state_out) {
  int bh = blockIdx.x;
  int b = bh >> 4;
  int h = bh & 15;
  int tid = threadIdx.x;
  int col = tid >> 2;
  int kq = tid & 3;

  __shared__ float qs[64], ks[64], vs[64], sc[2];
  float s[16];
#pragma unroll
  for (int i = 0; i < 16; i++) s[i] = 0.f;

  size_t vecbase = (size_t)b * T_ * 1024 + (size_t)h * 64;
  int bgbase = b * T_ * H_ + h;

  for (int t = 0; t < T_; t++) {
    size_t off = vecbase + (size_t)t * 1024;
    if (tid < 64)        qs[tid]       = q[off + tid];
    else if (tid < 128)  ks[tid - 64]  = k[off + tid - 64];
    else if (tid < 192)  vs[tid - 128] = v[off + tid - 128];
    else if (tid == 192) sc[0] = beta[bgbase + t * H_];
    else if (tid == 193) sc[1] = g[bgbase + t * H_];
    __syncthreads();

    float eg = expf(sc[1]);
    float bt = sc[0];

    float kv = 0.f;
#pragma unroll
    for (int i = 0; i < 16; i++) {
      s[i] *= eg;
      kv += ks[kq * 16 + i] * s[i];
    }
    kv += __shfl_xor_sync(0xffffffffu, kv, 1);
    kv += __shfl_xor_sync(0xffffffffu, kv, 2);

    float delta = (vs[col] - kv) * bt;

    float op = 0.f;
#pragma unroll
    for (int i = 0; i < 16; i++) {
      float kk = ks[kq * 16 + i];
      s[i] += kk * delta;
      op += qs[kq * 16 + i] * s[i];
    }
    op += __shfl_xor_sync(0xffffffffu, op, 1);
    op += __shfl_xor_sync(0xffffffffu, op, 2);
    if (kq == 0) o[off + col] = op;
    __syncthreads();
  }

  float* sp = state_out + (size_t)bh * 64 * 64;
#pragma unroll
  for (int i = 0; i < 16; i++) sp[(kq * 16 + i) * 64 + col] = s[i];
}

// ---------------------------------------------------------------------------
// SwiGLU
// ---------------------------------------------------------------------------
__global__ void __launch_bounds__(256) swiglu_kernel(
    const float* __restrict__ gy, float* __restrict__ u) {
  int idx = blockIdx.x * 256 + threadIdx.x;
  if (idx >= ROWS * I_) return;
  int row = idx / I_;
  int col = idx - row * I_;
  float gv = gy[(size_t)row * TWOI + col];
  float yv = gy[(size_t)row * TWOI + I_ + col];
  u[idx] = gv / (1.f + expf(-gv)) * yv;
}

// ---------------------------------------------------------------------------
extern "C" void kernel_launch(void* const* d_in, const int* in_sizes, int n_in,
                              void* d_out, int out_size) {
  const float* x           = (const float*)d_in[0];
  const float* attn_norm_w = (const float*)d_in[1];
  const float* Wq          = (const float*)d_in[2];
  const float* Wk          = (const float*)d_in[3];
  const float* Wv          = (const float*)d_in[4];
  const float* conv_q_w    = (const float*)d_in[5];
  const float* conv_k_w    = (const float*)d_in[6];
  const float* conv_v_w    = (const float*)d_in[7];
  const float* Wb          = (const float*)d_in[8];
  const float* Wa          = (const float*)d_in[9];
  const float* dt_bias     = (const float*)d_in[10];
  const float* A_log       = (const float*)d_in[11];
  const float* o_norm_w    = (const float*)d_in[12];
  const float* Wo          = (const float*)d_in[13];
  const float* mlp_norm_w  = (const float*)d_in[14];
  const float* Wg          = (const float*)d_in[15];
  const float* Wd          = (const float*)d_in[16];
  float* out = (float*)d_out;

  float* pool = nullptr;
  cudaGetSymbolAddress((void**)&pool, g_pool);
  __nv_bfloat16* bf = nullptr;
  cudaGetSymbolAddress((void**)&bf, g_bf);

  cudaFuncSetAttribute(bf16gemm_kernel,
                       cudaFuncAttributeMaxDynamicSharedMemorySize, GEMM_SMEM);

  float* hbuf = pool + OFF_H;
  float* qpre = pool + OFF_QPRE;
  float* kpre = pool + OFF_KPRE;
  float* vpre = pool + OFF_VPRE;
  float* qbuf = pool + OFF_Q;
  float* kbuf = pool + OFF_K;
  float* vbuf = pool + OFF_V;
  float* obuf = pool + OFF_O;
  float* h2   = pool + OFF_H2;
  float* h3   = pool + OFF_H3;
  float* gy   = pool + OFF_GY;
  float* ubuf = pool + OFF_U;
  float* bbuf = pool + OFF_BETA;
  float* gbuf = pool + OFF_G;

  // weight transpose+split
  wsplit_kernel<<<dim3(D_ / 32, D_ / 32), 256>>>(Wq, bf + BF_WQ, bf + BF_WQ + W1, D_, D_);
  wsplit_kernel<<<dim3(D_ / 32, D_ / 32), 256>>>(Wk, bf + BF_WK, bf + BF_WK + W1, D_, D_);
  wsplit_kernel<<<dim3(D_ / 32, D_ / 32), 256>>>(Wv, bf + BF_WV, bf + BF_WV + W1, D_, D_);
  wsplit_kernel<<<dim3(D_ / 32, D_ / 32), 256>>>(Wo, bf + BF_WO, bf + BF_WO + W1, D_, D_);
  wsplit_kernel<<<dim3(TWOI / 32, D_ / 32), 256>>>(Wg, bf + BF_WG, bf + BF_WG + SWG, D_, TWOI);
  wsplit_kernel<<<dim3(D_ / 32, I_ / 32), 256>>>(Wd, bf + BF_WD, bf + BF_WD + SWD, I_, D_);

  // 1. h = rmsnorm(x)
  rmsnorm_row_kernel<<<ROWS, 256>>>(x, attn_norm_w, hbuf);
  split_kernel<<<(int)(S1 / 4 / 256), 256>>>(hbuf, bf + BF_AH, bf + BF_AL, S1 / 4);

  // 2. q/k/v projections (HMMA)
  dim3 gSq(D_ / 128, ROWS / 128);
  bf16gemm_kernel<<<gSq, 256, GEMM_SMEM>>>(bf + BF_AH, bf + BF_AL,
      bf + BF_WQ, bf + BF_WQ + W1, nullptr, qpre, ROWS, D_, D_);
  bf16gemm_kernel<<<gSq, 256, GEMM_SMEM>>>(bf + BF_AH, bf + BF_AL,
      bf + BF_WK, bf + BF_WK + W1, nullptr, kpre, ROWS, D_, D_);
  bf16gemm_kernel<<<gSq, 256, GEMM_SMEM>>>(bf + BF_AH, bf + BF_AL,
      bf + BF_WV, bf + BF_WV + W1, nullptr, vpre, ROWS, D_, D_);

  // 3. gates
  betag_kernel<<<(ROWS * H_ * 32) / 256, 256>>>(hbuf, Wb, Wa, dt_bias, A_log,
                                                bbuf, gbuf);

  // 4. conv + SiLU
  int nel = ROWS * D_;
  conv_silu_kernel<<<nel / 256, 256>>>(qpre, conv_q_w, qbuf);
  conv_silu_kernel<<<nel / 256, 256>>>(kpre, conv_k_w, kbuf);
  conv_silu_kernel<<<nel / 256, 256>>>(vpre, conv_v_w, vbuf);

  // 5. l2norm
  int ngrp = ROWS * H_;
  int nblk64 = (ngrp * 32) / 256;
  norm64_kernel<<<nblk64, 256>>>(qbuf, nullptr, 0.125f, 0, ngrp);
  norm64_kernel<<<nblk64, 256>>>(kbuf, nullptr, 1.0f, 0, ngrp);

  // 6. scan
  scan_kernel<<<B_ * H_, 256>>>(qbuf, kbuf, vbuf, bbuf, gbuf, obuf, out + SZ);

  // 7. per-head RMSNorm
  norm64_kernel<<<nblk64, 256>>>(obuf, o_norm_w, 1.0f, 1, ngrp);

  // 8. h2 = o @ Wo + x
  split_kernel<<<(int)(S1 / 4 / 256), 256>>>(obuf, bf + BF_OH, bf + BF_OL, S1 / 4);
  bf16gemm_kernel<<<gSq, 256, GEMM_SMEM>>>(bf + BF_OH, bf + BF_OL,
      bf + BF_WO, bf + BF_WO + W1, x, h2, ROWS, D_, D_);

  // 9. h3 = rmsnorm(h2)
  rmsnorm_row_kernel<<<ROWS, 256>>>(h2, mlp_norm_w, h3);
  split_kernel<<<(int)(S1 / 4 / 256), 256>>>(h3, bf + BF_3H, bf + BF_3L, S1 / 4);

  // 10. gy = h3 @ Wg
  dim3 gSg(TWOI / 128, ROWS / 128);
  bf16gemm_kernel<<<gSg, 256, GEMM_SMEM>>>(bf + BF_3H, bf + BF_3L,
      bf + BF_WG, bf + BF_WG + SWG, nullptr, gy, ROWS, TWOI, D_);

  // 11. SwiGLU
  swiglu_kernel<<<(ROWS * I_) / 256, 256>>>(gy, ubuf);
  split_kernel<<<(int)(S2 / 4 / 256), 256>>>(ubuf, bf + BF_UH, bf + BF_UL, S2 / 4);

  // 12. out = u @ Wd + h2
  bf16gemm_kernel<<<gSq, 256, GEMM_SMEM>>>(bf + BF_UH, bf + BF_UL,
      bf + BF_WD, bf + BF_WD + SWD, h2, out, ROWS, D_, I_);
}

// round 9
// speedup vs baseline: 2.1882x; 1.4408x over previous
#include <cuda_runtime.h>
#include <cuda_bf16.h>
#include <math.h>
#include <stdint.h>

// ---------------------------------------------------------------------------
// GatedDeltaNet encoder block. HMMA (mma.sync bf16 hi/lo split) + ldmatrix.
// B=4, T=1024, D=1024, H=16, DK=DV=64, K_conv=4, I=2816
// out[0..4194304) = final hidden [B,T,D]; out[4194304..] = last_state
// ---------------------------------------------------------------------------

#define B_    4
#define T_    1024
#define D_    1024
#define H_    16
#define ROWS  (B_ * T_)          // 4096
#define I_    2816
#define TWOI  (2 * I_)           // 5632

static constexpr size_t SZ       = (size_t)ROWS * D_;        // 4194304
static constexpr size_t OFF_H    = 0 * SZ;
static constexpr size_t OFF_QPRE = 1 * SZ;
static constexpr size_t OFF_KPRE = 2 * SZ;
static constexpr size_t OFF_VPRE = 3 * SZ;
static constexpr size_t OFF_Q    = 4 * SZ;
static constexpr size_t OFF_K    = 5 * SZ;
static constexpr size_t OFF_V    = 6 * SZ;
static constexpr size_t OFF_O    = 7 * SZ;
static constexpr size_t OFF_H2   = 8 * SZ;
static constexpr size_t OFF_GY   = 9 * SZ;
static constexpr size_t OFF_BETA = OFF_GY + (size_t)ROWS * TWOI;
static constexpr size_t OFF_G    = OFF_BETA + (size_t)ROWS * H_;
static constexpr size_t POOL_SZ  = OFF_G + (size_t)ROWS * H_;

static __device__ float g_pool[POOL_SZ];

// bf16 scratch pool -------------------------------------------------------
static constexpr size_t S1  = (size_t)ROWS * D_;      // 4194304
static constexpr size_t S2  = (size_t)ROWS * I_;      // 11534336
static constexpr size_t W1  = (size_t)D_ * D_;        // 1048576
static constexpr size_t SWG = (size_t)TWOI * D_;      // 5767168  (Wg^T)
static constexpr size_t SWD = (size_t)D_ * I_;        // 2883584  (Wd^T)

static constexpr size_t BF_AH  = 0;
static constexpr size_t BF_AL  = 1 * S1;
static constexpr size_t BF_OH  = 2 * S1;
static constexpr size_t BF_OL  = 3 * S1;
static constexpr size_t BF_3H  = 4 * S1;
static constexpr size_t BF_3L  = 5 * S1;
static constexpr size_t BF_UH  = 6 * S1;
static constexpr size_t BF_UL  = 6 * S1 + S2;
static constexpr size_t BF_WQ  = 6 * S1 + 2 * S2;     // hi, then lo at +W1
static constexpr size_t BF_WK  = BF_WQ + 2 * W1;
static constexpr size_t BF_WV  = BF_WK + 2 * W1;
static constexpr size_t BF_WO  = BF_WV + 2 * W1;
static constexpr size_t BF_WG  = BF_WO + 2 * W1;      // hi, lo at +SWG
static constexpr size_t BF_WD  = BF_WG + 2 * SWG;     // hi, lo at +SWD
static constexpr size_t BF_SZ  = BF_WD + 2 * SWD;

static __device__ __nv_bfloat16 g_bf[BF_SZ];

// ---------------------------------------------------------------------------
// helpers
// ---------------------------------------------------------------------------
__device__ __forceinline__ uint32_t smem_u32(const void* p) {
  uint32_t r;
  asm("{ .reg .u64 t; cvta.to.shared.u64 t, %1; cvt.u32.u64 %0, t; }"
      : "=r"(r) : "l"(p));
  return r;
}

__device__ __forceinline__ void cp16(uint32_t dst, const void* src) {
  asm volatile("cp.async.cg.shared.global [%0], [%1], 16;"
               :: "r"(dst), "l"(src));
}

__device__ __forceinline__ void ldsm4(uint32_t* r, uint32_t addr) {
  asm volatile(
      "ldmatrix.sync.aligned.m8n8.x4.shared.b16 {%0,%1,%2,%3}, [%4];"
      : "=r"(r[0]), "=r"(r[1]), "=r"(r[2]), "=r"(r[3])
      : "r"(addr));
}

__device__ __forceinline__ void mma16816(float* d, const uint32_t* a,
                                         const uint32_t* b) {
  asm volatile(
      "mma.sync.aligned.m16n8k16.row.col.f32.bf16.bf16.f32 "
      "{%0,%1,%2,%3}, {%4,%5,%6,%7}, {%8,%9}, {%0,%1,%2,%3};"
      : "+f"(d[0]), "+f"(d[1]), "+f"(d[2]), "+f"(d[3])
      : "r"(a[0]), "r"(a[1]), "r"(a[2]), "r"(a[3]), "r"(b[0]), "r"(b[1]));
}

__device__ __forceinline__ void split1(float v, __nv_bfloat16& h,
                                       __nv_bfloat16& l) {
  h = __float2bfloat16_rn(v);
  l = __float2bfloat16_rn(v - __bfloat162float(h));
}

// ---------------------------------------------------------------------------
// HMMA bf16 GEMM: C[M,N] = (Ah+Al)[M,K] @ (Bh+Bl)^T  (+ Res)
// Tile 128x128, BK=32, 3-stage cp.async, ldmatrix fragment loads.
// 256 threads (8 warps 2x4), warp tile 64x32.
// smem rows 80B pitch (64B data + 16 pad) -> conflict-free LDSM.
// ---------------------------------------------------------------------------
static constexpr int TILE_B   = 10240;         // 128 rows * 80 B
static constexpr int STAGE_B  = 4 * TILE_B;    // Ah, Al, Bh, Bl
static constexpr int GEMM_SMEM = 3 * STAGE_B;  // 122880

__device__ __forceinline__ void load_stage(
    const __nv_bfloat16* __restrict__ Ah, const __nv_bfloat16* __restrict__ Al,
    const __nv_bfloat16* __restrict__ Bh, const __nv_bfloat16* __restrict__ Bl,
    int K, int m0, int n0, int k0, uint32_t sb, int stage, int tid) {
  uint32_t sdst = sb + stage * STAGE_B;
#pragma unroll
  for (int t = 0; t < 8; t++) {
    int idx = t * 256 + tid;        // 0..2047
    int tile = idx >> 9;            // 0..3
    int row = (idx >> 2) & 127;
    int ch = idx & 3;
    const __nv_bfloat16* base;
    int row0;
    if (tile == 0)      { base = Ah; row0 = m0; }
    else if (tile == 1) { base = Al; row0 = m0; }
    else if (tile == 2) { base = Bh; row0 = n0; }
    else                { base = Bl; row0 = n0; }
    const void* src = base + (size_t)(row0 + row) * K + k0 + ch * 8;
    cp16(sdst + tile * TILE_B + row * 80 + ch * 16, src);
  }
}

__global__ void __launch_bounds__(256, 1)
bf16gemm_kernel(const __nv_bfloat16* __restrict__ Ah,
                const __nv_bfloat16* __restrict__ Al,
                const __nv_bfloat16* __restrict__ Bh,
                const __nv_bfloat16* __restrict__ Bl,
                const float* __restrict__ Res, float* __restrict__ C,
                int M, int N, int K) {
  extern __shared__ char sm[];
  uint32_t sb = smem_u32(sm);
  const int tid = threadIdx.x;
  const int wid = tid >> 5;
  const int lid = tid & 31;
  const int gid = lid >> 2;   // 0..7
  const int tig = lid & 3;    // 0..3
  const int wm = wid >> 2;    // 0..1
  const int wn = wid & 3;     // 0..3
  const int m0 = blockIdx.y * 128;
  const int n0 = blockIdx.x * 128;
  const int nc = K >> 5;

  // ldmatrix lane sub-roles
  const int sub = lid >> 3;   // 0..3 (which 8x8 matrix this lane feeds)
  const int r8  = lid & 7;

  float acc[4][4][4];
#pragma unroll
  for (int i = 0; i < 4; i++)
#pragma unroll
    for (int j = 0; j < 4; j++)
#pragma unroll
      for (int r = 0; r < 4; r++) acc[i][j][r] = 0.f;

  load_stage(Ah, Al, Bh, Bl, K, m0, n0, 0, sb, 0, tid);
  asm volatile("cp.async.commit_group;");
  load_stage(Ah, Al, Bh, Bl, K, m0, n0, 32, sb, 1, tid);
  asm volatile("cp.async.commit_group;");

  // per-lane intra-tile offsets (k-offset added per ks)
  // A mats: {m0-7 k0-7, m8-15 k0-7, m0-7 k8-15, m8-15 k8-15}
  const uint32_t aLane = (uint32_t)(((sub & 1) * 8 + r8) * 80 + (sub >> 1) * 16);
  // B mats: {n0-7 k0-7, n0-7 k8-15, n8-15 k0-7, n8-15 k8-15}
  const uint32_t bLane = (uint32_t)(((sub >> 1) * 8 + r8) * 80 + (sub & 1) * 16);

  for (int c = 0; c < nc; c++) {
    asm volatile("cp.async.wait_group 1;");
    __syncthreads();
    if (c + 2 < nc)
      load_stage(Ah, Al, Bh, Bl, K, m0, n0, (c + 2) * 32, sb, (c + 2) % 3, tid);
    asm volatile("cp.async.commit_group;");

    uint32_t st = sb + (c % 3) * STAGE_B;
    uint32_t aBase = st + (uint32_t)(wm * 64) * 80 + aLane;
    uint32_t bBase = st + 2 * TILE_B + (uint32_t)(wn * 32) * 80 + bLane;
#pragma unroll
    for (int ks = 0; ks < 2; ks++) {
      uint32_t ko = ks * 32;  // 16 bf16 = 32 B
      uint32_t ah[4][4], al[4][4], bh[4][2], bl[4][2];
#pragma unroll
      for (int mi = 0; mi < 4; mi++) {
        uint32_t ad = aBase + ko + (uint32_t)(mi * 16) * 80;
        ldsm4(ah[mi], ad);
        ldsm4(al[mi], ad + TILE_B);
      }
#pragma unroll
      for (int np = 0; np < 2; np++) {  // ni pair {0,1} and {2,3}
        uint32_t bd = bBase + ko + (uint32_t)(np * 16) * 80;
        uint32_t th[4], tl[4];
        ldsm4(th, bd);
        ldsm4(tl, bd + TILE_B);
        bh[np * 2][0] = th[0]; bh[np * 2][1] = th[1];
        bh[np * 2 + 1][0] = th[2]; bh[np * 2 + 1][1] = th[3];
        bl[np * 2][0] = tl[0]; bl[np * 2][1] = tl[1];
        bl[np * 2 + 1][0] = tl[2]; bl[np * 2 + 1][1] = tl[3];
      }
#pragma unroll
      for (int mi = 0; mi < 4; mi++)
#pragma unroll
        for (int ni = 0; ni < 4; ni++) {
          mma16816(acc[mi][ni], ah[mi], bh[ni]);
          mma16816(acc[mi][ni], ah[mi], bl[ni]);
          mma16816(acc[mi][ni], al[mi], bh[ni]);
        }
    }
    __syncthreads();
  }

  const int mrow = m0 + wm * 64;
  const int ncol = n0 + wn * 32;
#pragma unroll
  for (int mi = 0; mi < 4; mi++) {
#pragma unroll
    for (int ni = 0; ni < 4; ni++) {
      int r0 = mrow + mi * 16 + gid;
      int cc = ncol + ni * 8 + tig * 2;
      float2 v0 = make_float2(acc[mi][ni][0], acc[mi][ni][1]);
      float2 v1 = make_float2(acc[mi][ni][2], acc[mi][ni][3]);
      if (Res != nullptr) {
        float2 r0v = *reinterpret_cast<const float2*>(Res + (size_t)r0 * N + cc);
        float2 r1v = *reinterpret_cast<const float2*>(Res + (size_t)(r0 + 8) * N + cc);
        v0.x += r0v.x; v0.y += r0v.y;
        v1.x += r1v.x; v1.y += r1v.y;
      }
      *reinterpret_cast<float2*>(C + (size_t)r0 * N + cc) = v0;
      *reinterpret_cast<float2*>(C + (size_t)(r0 + 8) * N + cc) = v1;
    }
  }
}

// ---------------------------------------------------------------------------
// Weight transpose + split: W[K,N] fp32 -> Th/Tl[N,K] bf16.
// ---------------------------------------------------------------------------
__global__ void __launch_bounds__(256) wsplit_kernel(
    const float* __restrict__ W, __nv_bfloat16* __restrict__ Th,
    __nv_bfloat16* __restrict__ Tl, int K, int N) {
  __shared__ float t[32][33];
  int n0 = blockIdx.x * 32, k0 = blockIdx.y * 32;
  int tx = threadIdx.x & 31, ty = threadIdx.x >> 5;
  for (int i = ty; i < 32; i += 8)
    t[i][tx] = W[(size_t)(k0 + i) * N + n0 + tx];
  __syncthreads();
  for (int i = ty; i < 32; i += 8) {
    float v = t[tx][i];
    __nv_bfloat16 h, l;
    split1(v, h, l);
    size_t o = (size_t)(n0 + i) * K + k0 + tx;
    Th[o] = h;
    Tl[o] = l;
  }
}

// ---------------------------------------------------------------------------
// RMSNorm over D=1024 per row, emits optional fp32 + bf16 hi/lo.
// ---------------------------------------------------------------------------
__global__ void __launch_bounds__(256) rmsnorm_split_kernel(
    const float* __restrict__ x, const float* __restrict__ w,
    float* __restrict__ y, __nv_bfloat16* __restrict__ yh,
    __nv_bfloat16* __restrict__ yl) {
  int row = blockIdx.x;
  int tid = threadIdx.x;
  const float4* xr = reinterpret_cast<const float4*>(x + (size_t)row * D_);
  float4 v = xr[tid];
  float ss = v.x * v.x + v.y * v.y + v.z * v.z + v.w * v.w;
#pragma unroll
  for (int o = 16; o > 0; o >>= 1) ss += __shfl_xor_sync(0xffffffffu, ss, o);
  __shared__ float red[8];
  if ((tid & 31) == 0) red[tid >> 5] = ss;
  __syncthreads();
  float tot = red[0] + red[1] + red[2] + red[3] + red[4] + red[5] + red[6] + red[7];
  float r = rsqrtf(tot * (1.0f / 1024.0f) + 1e-6f);
  float4 wv = reinterpret_cast<const float4*>(w)[tid];
  float4 ov = make_float4(v.x * r * wv.x, v.y * r * wv.y,
                          v.z * r * wv.z, v.w * r * wv.w);
  if (y != nullptr)
    reinterpret_cast<float4*>(y + (size_t)row * D_)[tid] = ov;
  __nv_bfloat16 h0, h1, h2, h3, l0, l1, l2, l3;
  split1(ov.x, h0, l0); split1(ov.y, h1, l1);
  split1(ov.z, h2, l2); split1(ov.w, h3, l3);
  size_t o4 = (size_t)row * (D_ / 2) + tid * 2;
  reinterpret_cast<__nv_bfloat162*>(yh)[o4 + 0] = __nv_bfloat162(h0, h1);
  reinterpret_cast<__nv_bfloat162*>(yh)[o4 + 1] = __nv_bfloat162(h2, h3);
  reinterpret_cast<__nv_bfloat162*>(yl)[o4 + 0] = __nv_bfloat162(l0, l1);
  reinterpret_cast<__nv_bfloat162*>(yl)[o4 + 1] = __nv_bfloat162(l2, l3);
}

// ---------------------------------------------------------------------------
// Causal depthwise conv1d (K=4) + SiLU.
// ---------------------------------------------------------------------------
__global__ void __launch_bounds__(256) conv_silu_kernel(
    const float* __restrict__ x, const float* __restrict__ w,
    float* __restrict__ y) {
  int idx = blockIdx.x * 256 + threadIdx.x;
  if (idx >= ROWS * D_) return;
  int c = idx & 1023;
  int t = (idx >> 10) & 1023;
  float acc = 0.f;
#pragma unroll
  for (int i = 0; i < 4; i++) {
    int tt = t + i - 3;
    if (tt >= 0) acc += x[idx + (i - 3) * 1024] * w[c * 4 + i];
  }
  y[idx] = acc / (1.f + expf(-acc));
}

// ---------------------------------------------------------------------------
// Per-64-group l2norm, 1 warp / group, in place fp32.
// ---------------------------------------------------------------------------
__global__ void __launch_bounds__(256) norm64_l2_kernel(
    float* __restrict__ x, float scale, int ngroups) {
  int gw = (blockIdx.x * blockDim.x + threadIdx.x) >> 5;
  int lane = threadIdx.x & 31;
  if (gw >= ngroups) return;
  float* p = x + (size_t)gw * 64;
  float a = p[lane];
  float b = p[lane + 32];
  float ss = a * a + b * b;
#pragma unroll
  for (int o = 16; o > 0; o >>= 1) ss += __shfl_xor_sync(0xffffffffu, ss, o);
  float r = rsqrtf(ss + 1e-6f) * scale;
  p[lane] = a * r;
  p[lane + 32] = b * r;
}

// ---------------------------------------------------------------------------
// Per-64-group RMSNorm -> bf16 hi/lo, 1 warp / group.
// ---------------------------------------------------------------------------
__global__ void __launch_bounds__(256) norm64_rms_split_kernel(
    const float* __restrict__ x, const float* __restrict__ w,
    __nv_bfloat16* __restrict__ yh, __nv_bfloat16* __restrict__ yl,
    int ngroups) {
  int gw = (blockIdx.x * blockDim.x + threadIdx.x) >> 5;
  int lane = threadIdx.x & 31;
  if (gw >= ngroups) return;
  const float* p = x + (size_t)gw * 64;
  float a = p[lane];
  float b = p[lane + 32];
  float ss = a * a + b * b;
#pragma unroll
  for (int o = 16; o > 0; o >>= 1) ss += __shfl_xor_sync(0xffffffffu, ss, o);
  float r = rsqrtf(ss * (1.f / 64.f) + 1e-6f);
  a *= r * w[lane];
  b *= r * w[lane + 32];
  __nv_bfloat16 h, l;
  split1(a, h, l);
  yh[(size_t)gw * 64 + lane] = h;
  yl[(size_t)gw * 64 + lane] = l;
  split1(b, h, l);
  yh[(size_t)gw * 64 + lane + 32] = h;
  yl[(size_t)gw * 64 + lane + 32] = l;
}

// ---------------------------------------------------------------------------
// beta/g gates: one block per row, h staged in smem.
// ---------------------------------------------------------------------------
__global__ void __launch_bounds__(256) betag_kernel(
    const float* __restrict__ h, const float* __restrict__ Wb,
    const float* __restrict__ Wa, const float* __restrict__ dt_bias,
    const float* __restrict__ A_log, float* __restrict__ beta,
    float* __restrict__ gout) {
  __shared__ float hs[D_];
  __shared__ float pb[256], pa[256];
  int row = blockIdx.x;
  int tid = threadIdx.x;
  reinterpret_cast<float4*>(hs)[tid] =
      reinterpret_cast<const float4*>(h + (size_t)row * D_)[tid];
  __syncthreads();
  int head = tid & 15;
  int chunk = tid >> 4;   // 0..15, 64 k each
  float sb = 0.f, sa = 0.f;
  int base = chunk * 64;
#pragma unroll 8
  for (int i = 0; i < 64; i++) {
    float hv = hs[base + i];
    int wi = (base + i) * 16 + head;
    sb += hv * Wb[wi];
    sa += hv * Wa[wi];
  }
  pb[tid] = sb;
  pa[tid] = sa;
  __syncthreads();
  if (tid < 16) {
    float b = 0.f, a = 0.f;
#pragma unroll
    for (int c = 0; c < 16; c++) {
      b += pb[c * 16 + tid];
      a += pa[c * 16 + tid];
    }
    beta[row * H_ + tid] = 2.f / (1.f + expf(-b));
    float z = a + dt_bias[tid];
    float sp = (z > 20.f) ? z : log1pf(expf(z));
    gout[row * H_ + tid] = -expf(A_log[tid]) * sp;
  }
}

// ---------------------------------------------------------------------------
// Sequential gated delta-rule scan, double-buffered prefetch, 1 sync/step.
// ---------------------------------------------------------------------------
__global__ void __launch_bounds__(256) scan_kernel(
    const float* __restrict__ q, const float* __restrict__ k,
    const float* __restrict__ v, const float* __restrict__ beta,
    const float* __restrict__ g, float* __restrict__ o,
    float* __restrict__ state_out) {
  int bh = blockIdx.x;
  int b = bh >> 4;
  int h = bh & 15;
  int tid = threadIdx.x;
  int col = tid >> 2;
  int kq = tid & 3;

  __shared__ float qs[2][64], ks[2][64], vs[2][64], sc[2][2];
  float s[16];
#pragma unroll
  for (int i = 0; i < 16; i++) s[i] = 0.f;

  size_t vecbase = (size_t)b * T_ * 1024 + (size_t)h * 64;
  int bgbase = b * T_ * H_ + h;

  const float* src = nullptr;
  int stride = 0;
  if (tid < 64)       { src = q + vecbase + tid;        stride = 1024; }
  else if (tid < 128) { src = k + vecbase + tid - 64;   stride = 1024; }
  else if (tid < 192) { src = v + vecbase + tid - 128;  stride = 1024; }
  else if (tid == 192){ src = beta + bgbase;            stride = H_; }
  else if (tid == 193){ src = g + bgbase;               stride = H_; }

  float pre = (src != nullptr) ? src[0] : 0.f;
  int buf = 0;

  for (int t = 0; t < T_; t++) {
    if (tid < 64)        qs[buf][tid] = pre;
    else if (tid < 128)  ks[buf][tid - 64] = pre;
    else if (tid < 192)  vs[buf][tid - 128] = pre;
    else if (tid < 194)  sc[buf][tid - 192] = pre;
    __syncthreads();
    if (t + 1 < T_ && src != nullptr) pre = src[(size_t)(t + 1) * stride];

    float eg = expf(sc[buf][1]);
    float bt = sc[buf][0];

    float kv = 0.f;
#pragma unroll
    for (int i = 0; i < 16; i++) {
      s[i] *= eg;
      kv += ks[buf][kq * 16 + i] * s[i];
    }
    kv += __shfl_xor_sync(0xffffffffu, kv, 1);
    kv += __shfl_xor_sync(0xffffffffu, kv, 2);

    float delta = (vs[buf][col] - kv) * bt;

    float op = 0.f;
#pragma unroll
    for (int i = 0; i < 16; i++) {
      float kk = ks[buf][kq * 16 + i];
      s[i] += kk * delta;
      op += qs[buf][kq * 16 + i] * s[i];
    }
    op += __shfl_xor_sync(0xffffffffu, op, 1);
    op += __shfl_xor_sync(0xffffffffu, op, 2);
    if (kq == 0) o[vecbase + (size_t)t * 1024 + col] = op;
    buf ^= 1;
  }

  float* sp = state_out + (size_t)bh * 64 * 64;
#pragma unroll
  for (int i = 0; i < 16; i++) sp[(kq * 16 + i) * 64 + col] = s[i];
}

// ---------------------------------------------------------------------------
// SwiGLU -> bf16 hi/lo
// ---------------------------------------------------------------------------
__global__ void __launch_bounds__(256) swiglu_split_kernel(
    const float* __restrict__ gy, __nv_bfloat16* __restrict__ uh,
    __nv_bfloat16* __restrict__ ul) {
  int idx = blockIdx.x * 256 + threadIdx.x;
  if (idx >= ROWS * I_) return;
  int row = idx / I_;
  int col = idx - row * I_;
  float gv = gy[(size_t)row * TWOI + col];
  float yv = gy[(size_t)row * TWOI + I_ + col];
  float u = gv / (1.f + expf(-gv)) * yv;
  __nv_bfloat16 h, l;
  split1(u, h, l);
  uh[idx] = h;
  ul[idx] = l;
}

// ---------------------------------------------------------------------------
extern "C" void kernel_launch(void* const* d_in, const int* in_sizes, int n_in,
                              void* d_out, int out_size) {
  const float* x           = (const float*)d_in[0];
  const float* attn_norm_w = (const float*)d_in[1];
  const float* Wq          = (const float*)d_in[2];
  const float* Wk          = (const float*)d_in[3];
  const float* Wv          = (const float*)d_in[4];
  const float* conv_q_w    = (const float*)d_in[5];
  const float* conv_k_w    = (const float*)d_in[6];
  const float* conv_v_w    = (const float*)d_in[7];
  const float* Wb          = (const float*)d_in[8];
  const float* Wa          = (const float*)d_in[9];
  const float* dt_bias     = (const float*)d_in[10];
  const float* A_log       = (const float*)d_in[11];
  const float* o_norm_w    = (const float*)d_in[12];
  const float* Wo          = (const float*)d_in[13];
  const float* mlp_norm_w  = (const float*)d_in[14];
  const float* Wg          = (const float*)d_in[15];
  const float* Wd          = (const float*)d_in[16];
  float* out = (float*)d_out;

  float* pool = nullptr;
  cudaGetSymbolAddress((void**)&pool, g_pool);
  __nv_bfloat16* bf = nullptr;
  cudaGetSymbolAddress((void**)&bf, g_bf);

  cudaFuncSetAttribute(bf16gemm_kernel,
                       cudaFuncAttributeMaxDynamicSharedMemorySize, GEMM_SMEM);

  float* hbuf = pool + OFF_H;
  float* qpre = pool + OFF_QPRE;
  float* kpre = pool + OFF_KPRE;
  float* vpre = pool + OFF_VPRE;
  float* qbuf = pool + OFF_Q;
  float* kbuf = pool + OFF_K;
  float* vbuf = pool + OFF_V;
  float* obuf = pool + OFF_O;
  float* h2   = pool + OFF_H2;
  float* gy   = pool + OFF_GY;
  float* bbuf = pool + OFF_BETA;
  float* gbuf = pool + OFF_G;

  // launch 0: h = rmsnorm(x) -> fp32 + bf16 hi/lo
  rmsnorm_split_kernel<<<ROWS, 256>>>(x, attn_norm_w, hbuf,
                                      bf + BF_AH, bf + BF_AL);
  // launches 1-4: weight splits needed for QKV + Wo
  wsplit_kernel<<<dim3(D_ / 32, D_ / 32), 256>>>(Wq, bf + BF_WQ, bf + BF_WQ + W1, D_, D_);
  wsplit_kernel<<<dim3(D_ / 32, D_ / 32), 256>>>(Wk, bf + BF_WK, bf + BF_WK + W1, D_, D_);
  wsplit_kernel<<<dim3(D_ / 32, D_ / 32), 256>>>(Wv, bf + BF_WV, bf + BF_WV + W1, D_, D_);
  wsplit_kernel<<<dim3(D_ / 32, D_ / 32), 256>>>(Wo, bf + BF_WO, bf + BF_WO + W1, D_, D_);

  // launch 5 (ncu -s 5 profiles this): first GEMM
  dim3 gSq(D_ / 128, ROWS / 128);
  bf16gemm_kernel<<<gSq, 256, GEMM_SMEM>>>(bf + BF_AH, bf + BF_AL,
      bf + BF_WQ, bf + BF_WQ + W1, nullptr, qpre, ROWS, D_, D_);
  bf16gemm_kernel<<<gSq, 256, GEMM_SMEM>>>(bf + BF_AH, bf + BF_AL,
      bf + BF_WK, bf + BF_WK + W1, nullptr, kpre, ROWS, D_, D_);
  bf16gemm_kernel<<<gSq, 256, GEMM_SMEM>>>(bf + BF_AH, bf + BF_AL,
      bf + BF_WV, bf + BF_WV + W1, nullptr, vpre, ROWS, D_, D_);

  // remaining weight splits (overlap-friendly position)
  wsplit_kernel<<<dim3(TWOI / 32, D_ / 32), 256>>>(Wg, bf + BF_WG, bf + BF_WG + SWG, D_, TWOI);
  wsplit_kernel<<<dim3(D_ / 32, I_ / 32), 256>>>(Wd, bf + BF_WD, bf + BF_WD + SWD, I_, D_);

  // gates
  betag_kernel<<<ROWS, 256>>>(hbuf, Wb, Wa, dt_bias, A_log, bbuf, gbuf);

  // conv + SiLU
  int nel = ROWS * D_;
  conv_silu_kernel<<<nel / 256, 256>>>(qpre, conv_q_w, qbuf);
  conv_silu_kernel<<<nel / 256, 256>>>(kpre, conv_k_w, kbuf);
  conv_silu_kernel<<<nel / 256, 256>>>(vpre, conv_v_w, vbuf);

  // l2norm
  int ngrp = ROWS * H_;
  int nblk64 = (ngrp * 32) / 256;
  norm64_l2_kernel<<<nblk64, 256>>>(qbuf, 0.125f, ngrp);
  norm64_l2_kernel<<<nblk64, 256>>>(kbuf, 1.0f, ngrp);

  // scan
  scan_kernel<<<B_ * H_, 256>>>(qbuf, kbuf, vbuf, bbuf, gbuf, obuf, out + SZ);

  // per-head RMSNorm -> bf16 hi/lo
  norm64_rms_split_kernel<<<nblk64, 256>>>(obuf, o_norm_w,
                                           bf + BF_OH, bf + BF_OL, ngrp);

  // h2 = o @ Wo + x
  bf16gemm_kernel<<<gSq, 256, GEMM_SMEM>>>(bf + BF_OH, bf + BF_OL,
      bf + BF_WO, bf + BF_WO + W1, x, h2, ROWS, D_, D_);

  // h3 = rmsnorm(h2) -> bf16 hi/lo only
  rmsnorm_split_kernel<<<ROWS, 256>>>(h2, mlp_norm_w, nullptr,
                                      bf + BF_3H, bf + BF_3L);

  // gy = h3 @ Wg
  dim3 gSg(TWOI / 128, ROWS / 128);
  bf16gemm_kernel<<<gSg, 256, GEMM_SMEM>>>(bf + BF_3H, bf + BF_3L,
      bf + BF_WG, bf + BF_WG + SWG, nullptr, gy, ROWS, TWOI, D_);

  // SwiGLU -> bf16 hi/lo
  swiglu_split_kernel<<<(ROWS * I_) / 256, 256>>>(gy, bf + BF_UH, bf + BF_UL);

  // out = u @ Wd + h2
  bf16gemm_kernel<<<gSq, 256, GEMM_SMEM>>>(bf + BF_UH, bf + BF_UL,
      bf + BF_WD, bf + BF_WD + SWD, h2, out, ROWS, D_, I_);
}

// round 11
// speedup vs baseline: 2.8344x; 1.2953x over previous
#include <cuda_runtime.h>
#include <cuda_bf16.h>
#include <math.h>
#include <stdint.h>

// ---------------------------------------------------------------------------
// GatedDeltaNet encoder. HMMA bf16 hi/lo GEMMs, blocked-tile global layout,
// cp.async.bulk + mbarrier pipeline. B=4,T=1024,D=1024,H=16,I=2816.
// out[0..4194304) = hidden; out[4194304..] = last_state.
// ---------------------------------------------------------------------------

#define B_    4
#define T_    1024
#define D_    1024
#define H_    16
#define ROWS  (B_ * T_)          // 4096
#define I_    2816
#define TWOI  (2 * I_)           // 5632

static constexpr size_t SZ        = (size_t)ROWS * D_;       // 4194304
static constexpr size_t OFF_H     = 0 * SZ;
static constexpr size_t OFF_QKV   = 1 * SZ;                  // [4096,3072]
static constexpr size_t OFF_Q     = 4 * SZ;
static constexpr size_t OFF_K     = 5 * SZ;
static constexpr size_t OFF_V     = 6 * SZ;
static constexpr size_t OFF_O     = 7 * SZ;
static constexpr size_t OFF_H2    = 8 * SZ;
static constexpr size_t OFF_GY    = 9 * SZ;                  // [4096,5632]
static constexpr size_t OFF_BETA  = OFF_GY + (size_t)ROWS * TWOI;
static constexpr size_t OFF_G     = OFF_BETA + (size_t)ROWS * H_;
static constexpr size_t POOL_SZ   = OFF_G + (size_t)ROWS * H_;

static __device__ __align__(256) float g_pool[POOL_SZ];

// bf16 blocked scratch --------------------------------------------------------
static constexpr size_t S1  = (size_t)ROWS * D_;      // 4194304
static constexpr size_t S2  = (size_t)ROWS * I_;      // 11534336
static constexpr size_t W1  = (size_t)D_ * D_;        // 1048576
static constexpr size_t SWG = (size_t)TWOI * D_;
static constexpr size_t SWD = (size_t)D_ * I_;

static constexpr size_t BF_AH  = 0;
static constexpr size_t BF_AL  = 1 * S1;
static constexpr size_t BF_OH  = 2 * S1;
static constexpr size_t BF_OL  = 3 * S1;
static constexpr size_t BF_3H  = 4 * S1;
static constexpr size_t BF_3L  = 5 * S1;
static constexpr size_t BF_UH  = 6 * S1;
static constexpr size_t BF_UL  = 6 * S1 + S2;
static constexpr size_t BF_WQKVH = 6 * S1 + 2 * S2;   // 3*W1 (q,k,v tiles)
static constexpr size_t BF_WQKVL = BF_WQKVH + 3 * W1;
static constexpr size_t BF_WOH = BF_WQKVL + 3 * W1;
static constexpr size_t BF_WOL = BF_WOH + W1;
static constexpr size_t BF_WGH = BF_WOL + W1;
static constexpr size_t BF_WGL = BF_WGH + SWG;
static constexpr size_t BF_WDH = BF_WGL + SWG;
static constexpr size_t BF_WDL = BF_WDH + SWD;
static constexpr size_t BF_SZ  = BF_WDL + SWD;

static __device__ __align__(256) __nv_bfloat16 g_bf[BF_SZ];

// ---------------------------------------------------------------------------
// helpers
// ---------------------------------------------------------------------------
__device__ __forceinline__ uint32_t smem_u32(const void* p) {
  uint32_t r;
  asm("{ .reg .u64 t; cvta.to.shared.u64 t, %1; cvt.u32.u64 %0, t; }"
      : "=r"(r) : "l"(p));
  return r;
}

__device__ __forceinline__ void mbar_init(uint32_t a, uint32_t c) {
  asm volatile("mbarrier.init.shared.b64 [%0], %1;" :: "r"(a), "r"(c) : "memory");
}
__device__ __forceinline__ void mbar_wait(uint32_t a, uint32_t par) {
  asm volatile(
      "{\n\t.reg .pred P;\n"
      "W%=:\n\tmbarrier.try_wait.parity.acquire.cta.shared::cta.b64 P, [%0], %1, 0x989680;\n"
      "\t@!P bra W%=;\n\t}"
      :: "r"(a), "r"(par) : "memory");
}
__device__ __forceinline__ void expect_tx(uint32_t bar, uint32_t bytes) {
  asm volatile("mbarrier.arrive.expect_tx.shared.b64 _, [%0], %1;"
               :: "r"(bar), "r"(bytes) : "memory");
}
__device__ __forceinline__ void bulk_ld(uint32_t dst, const void* src,
                                        uint32_t bytes, uint32_t bar) {
  asm volatile(
      "cp.async.bulk.shared::cluster.global.mbarrier::complete_tx::bytes "
      "[%0], [%1], %2, [%3];"
      :: "r"(dst), "l"(src), "r"(bytes), "r"(bar) : "memory");
}

__device__ __forceinline__ void ldsm4(uint32_t* r, uint32_t addr) {
  asm volatile(
      "ldmatrix.sync.aligned.m8n8.x4.shared.b16 {%0,%1,%2,%3}, [%4];"
      : "=r"(r[0]), "=r"(r[1]), "=r"(r[2]), "=r"(r[3])
      : "r"(addr));
}

__device__ __forceinline__ void mma16816(float* d, const uint32_t* a,
                                         const uint32_t* b) {
  asm volatile(
      "mma.sync.aligned.m16n8k16.row.col.f32.bf16.bf16.f32 "
      "{%0,%1,%2,%3}, {%4,%5,%6,%7}, {%8,%9}, {%0,%1,%2,%3};"
      : "+f"(d[0]), "+f"(d[1]), "+f"(d[2]), "+f"(d[3])
      : "r"(a[0]), "r"(a[1]), "r"(a[2]), "r"(a[3]), "r"(b[0]), "r"(b[1]));
}

__device__ __forceinline__ void split1(float v, __nv_bfloat16& h,
                                       __nv_bfloat16& l) {
  h = __float2bfloat16_rn(v);
  l = __float2bfloat16_rn(v - __bfloat162float(h));
}

// Blocked tile element offset: matrix [Nrows, K] stored as
// [Nrows/128][K/32] tiles of 128x32 bf16 (8192 B), rows 64 B, 16B units
// swizzled by u ^= (r>>1)&3.
__device__ __forceinline__ size_t blk_off(int n, int k, int nK) {
  int nb = n >> 7, r = n & 127, kb = k >> 5;
  int unit = (k >> 3) & 3;
  int su = unit ^ ((r >> 1) & 3);
  size_t byte = ((size_t)(nb * nK + kb)) * 8192 + r * 64 + su * 16 + (k & 7) * 2;
  return byte >> 1;  // element index
}

// ---------------------------------------------------------------------------
// GEMM: C[M,N] = (Ah+Al)[M,K] @ (Bh+Bl)[N,K]^T (+Res). Blocked inputs.
// CTA tile 256x128, BK=32, 3 stages, cp.async.bulk + mbarrier.
// 8 warps (4m x 2n), warp tile 64x64. grid (N/128, M/256).
// ---------------------------------------------------------------------------
static constexpr int STG = 49152;                 // 2A-hi + 2A-lo + B-hi + B-lo
static constexpr int GEMM_SMEM = 1024 + 3 * STG;  // 148480

__global__ void __launch_bounds__(256, 1)
bf16gemm_kernel(const __nv_bfloat16* __restrict__ Ah,
                const __nv_bfloat16* __restrict__ Al,
                const __nv_bfloat16* __restrict__ Bh,
                const __nv_bfloat16* __restrict__ Bl,
                const float* __restrict__ Res, float* __restrict__ C,
                int N, int nK) {
  extern __shared__ __align__(16) char sm[];
  uint32_t sb = smem_u32(sm);
  const int tid = threadIdx.x;
  const int wid = tid >> 5, lid = tid & 31;
  const int gid = lid >> 2, tig = lid & 3;
  const int sub = lid >> 3, r8 = lid & 7;
  const int wm = wid >> 1, wn = wid & 1;
  const int mblk0 = blockIdx.y * 2;
  const int nblk = blockIdx.x;
  const int nc = nK;
  const int sx = (r8 >> 1) & 3;

  if (tid == 0) {
    mbar_init(sb + 0, 1);
    mbar_init(sb + 16, 1);
    mbar_init(sb + 32, 1);
  }
  __syncthreads();

  float acc[4][8][4];
#pragma unroll
  for (int i = 0; i < 4; i++)
#pragma unroll
    for (int j = 0; j < 8; j++)
#pragma unroll
      for (int r = 0; r < 4; r++) acc[i][j][r] = 0.f;

  if (tid == 0) {
#pragma unroll
    for (int s = 0; s < 3; s++) {
      uint32_t bar = sb + s * 16;
      uint32_t d = sb + 1024 + s * STG;
      expect_tx(bar, 49152);
      bulk_ld(d,         Ah + ((size_t)(mblk0 * nK + s)) * 4096, 8192, bar);
      bulk_ld(d + 8192,  Ah + ((size_t)((mblk0 + 1) * nK + s)) * 4096, 8192, bar);
      bulk_ld(d + 16384, Al + ((size_t)(mblk0 * nK + s)) * 4096, 8192, bar);
      bulk_ld(d + 24576, Al + ((size_t)((mblk0 + 1) * nK + s)) * 4096, 8192, bar);
      bulk_ld(d + 32768, Bh + ((size_t)(nblk * nK + s)) * 4096, 8192, bar);
      bulk_ld(d + 40960, Bl + ((size_t)(nblk * nK + s)) * 4096, 8192, bar);
    }
  }

  const uint32_t aRow = (uint32_t)((wm & 1) * 64 + (sub & 1) * 8 + r8) * 64;
  const uint32_t aTile = (uint32_t)(wm >> 1) * 8192;
  const uint32_t bRow = (uint32_t)(wn * 64 + (sub >> 1) * 8 + r8) * 64;

  for (int c = 0; c < nc; c++) {
    int st = c % 3;
    mbar_wait(sb + st * 16, (c / 3) & 1);

    uint32_t stage = sb + 1024 + st * STG;
    uint32_t aB = stage + aTile + aRow;
    uint32_t bB = stage + 32768 + bRow;
#pragma unroll
    for (int ks = 0; ks < 2; ks++) {
      uint32_t ua = (uint32_t)((ks * 2 + (sub >> 1)) ^ sx) << 4;
      uint32_t ub = (uint32_t)((ks * 2 + (sub & 1)) ^ sx) << 4;
      uint32_t ah[4][4], al[4][4], bh[8][2], bl[8][2];
#pragma unroll
      for (int mi = 0; mi < 4; mi++) {
        uint32_t ad = aB + mi * 1024 + ua;
        ldsm4(ah[mi], ad);
        ldsm4(al[mi], ad + 16384);
      }
#pragma unroll
      for (int np = 0; np < 4; np++) {
        uint32_t bd = bB + np * 1024 + ub;
        uint32_t th[4], tl[4];
        ldsm4(th, bd);
        ldsm4(tl, bd + 8192);
        bh[np * 2][0] = th[0]; bh[np * 2][1] = th[1];
        bh[np * 2 + 1][0] = th[2]; bh[np * 2 + 1][1] = th[3];
        bl[np * 2][0] = tl[0]; bl[np * 2][1] = tl[1];
        bl[np * 2 + 1][0] = tl[2]; bl[np * 2 + 1][1] = tl[3];
      }
#pragma unroll
      for (int mi = 0; mi < 4; mi++)
#pragma unroll
        for (int ni = 0; ni < 8; ni++) {
          mma16816(acc[mi][ni], ah[mi], bh[ni]);
          mma16816(acc[mi][ni], ah[mi], bl[ni]);
          mma16816(acc[mi][ni], al[mi], bh[ni]);
        }
    }
    __syncthreads();
    if (tid == 0 && c + 3 < nc) {
      int cc = c + 3;
      uint32_t bar = sb + st * 16;
      uint32_t d = sb + 1024 + st * STG;
      expect_tx(bar, 49152);
      bulk_ld(d,         Ah + ((size_t)(mblk0 * nK + cc)) * 4096, 8192, bar);
      bulk_ld(d + 8192,  Ah + ((size_t)((mblk0 + 1) * nK + cc)) * 4096, 8192, bar);
      bulk_ld(d + 16384, Al + ((size_t)(mblk0 * nK + cc)) * 4096, 8192, bar);
      bulk_ld(d + 24576, Al + ((size_t)((mblk0 + 1) * nK + cc)) * 4096, 8192, bar);
      bulk_ld(d + 32768, Bh + ((size_t)(nblk * nK + cc)) * 4096, 8192, bar);
      bulk_ld(d + 40960, Bl + ((size_t)(nblk * nK + cc)) * 4096, 8192, bar);
    }
  }

  const int mrow = blockIdx.y * 256 + wm * 64;
  const int ncol = nblk * 128 + wn * 64;
#pragma unroll
  for (int mi = 0; mi < 4; mi++) {
#pragma unroll
    for (int ni = 0; ni < 8; ni++) {
      int r0 = mrow + mi * 16 + gid;
      int cc = ncol + ni * 8 + tig * 2;
      float2 v0 = make_float2(acc[mi][ni][0], acc[mi][ni][1]);
      float2 v1 = make_float2(acc[mi][ni][2], acc[mi][ni][3]);
      if (Res != nullptr) {
        float2 a0 = *reinterpret_cast<const float2*>(Res + (size_t)r0 * N + cc);
        float2 a1 = *reinterpret_cast<const float2*>(Res + (size_t)(r0 + 8) * N + cc);
        v0.x += a0.x; v0.y += a0.y;
        v1.x += a1.x; v1.y += a1.y;
      }
      *reinterpret_cast<float2*>(C + (size_t)r0 * N + cc) = v0;
      *reinterpret_cast<float2*>(C + (size_t)(r0 + 8) * N + cc) = v1;
    }
  }
}

// ---------------------------------------------------------------------------
// Weight transpose + split -> blocked: W[K,N] fp32 -> Th/Tl blocked [N,K].
// ---------------------------------------------------------------------------
__global__ void __launch_bounds__(256) wsplit_kernel(
    const float* __restrict__ W, __nv_bfloat16* __restrict__ Th,
    __nv_bfloat16* __restrict__ Tl, int K, int N, int nK) {
  __shared__ float t[32][33];
  int n0 = blockIdx.x * 32, k0 = blockIdx.y * 32;
  int tx = threadIdx.x & 31, ty = threadIdx.x >> 5;
  for (int i = ty; i < 32; i += 8)
    t[i][tx] = W[(size_t)(k0 + i) * N + n0 + tx];
  __syncthreads();
  for (int i = ty; i < 32; i += 8) {
    float v = t[tx][i];  // W[k0+tx][n0+i]
    __nv_bfloat16 h, l;
    split1(v, h, l);
    size_t o = blk_off(n0 + i, k0 + tx, nK);
    Th[o] = h;
    Tl[o] = l;
  }
}

// ---------------------------------------------------------------------------
// RMSNorm per row -> optional fp32 + blocked bf16 hi/lo (nK = 32).
// ---------------------------------------------------------------------------
__global__ void __launch_bounds__(256) rmsnorm_split_kernel(
    const float* __restrict__ x, const float* __restrict__ w,
    float* __restrict__ y, __nv_bfloat16* __restrict__ yh,
    __nv_bfloat16* __restrict__ yl) {
  int row = blockIdx.x;
  int tid = threadIdx.x;
  const float4* xr = reinterpret_cast<const float4*>(x + (size_t)row * D_);
  float4 v = xr[tid];
  float ss = v.x * v.x + v.y * v.y + v.z * v.z + v.w * v.w;
#pragma unroll
  for (int o = 16; o > 0; o >>= 1) ss += __shfl_xor_sync(0xffffffffu, ss, o);
  __shared__ float red[8];
  if ((tid & 31) == 0) red[tid >> 5] = ss;
  __syncthreads();
  float tot = red[0] + red[1] + red[2] + red[3] + red[4] + red[5] + red[6] + red[7];
  float r = rsqrtf(tot * (1.0f / 1024.0f) + 1e-6f);
  float4 wv = reinterpret_cast<const float4*>(w)[tid];
  float4 ov = make_float4(v.x * r * wv.x, v.y * r * wv.y,
                          v.z * r * wv.z, v.w * r * wv.w);
  if (y != nullptr)
    reinterpret_cast<float4*>(y + (size_t)row * D_)[tid] = ov;
  __nv_bfloat16 h0, h1, h2, h3, l0, l1, l2, l3;
  split1(ov.x, h0, l0); split1(ov.y, h1, l1);
  split1(ov.z, h2, l2); split1(ov.w, h3, l3);
  size_t e = blk_off(row, tid * 4, 32);  // 8B-aligned start (k0 mult of 4)
  uint32_t p0 = (uint32_t)*(uint16_t*)&h0 | ((uint32_t)*(uint16_t*)&h1 << 16);
  uint32_t p1 = (uint32_t)*(uint16_t*)&h2 | ((uint32_t)*(uint16_t*)&h3 << 16);
  *reinterpret_cast<uint2*>(yh + e) = make_uint2(p0, p1);
  uint32_t q0 = (uint32_t)*(uint16_t*)&l0 | ((uint32_t)*(uint16_t*)&l1 << 16);
  uint32_t q1 = (uint32_t)*(uint16_t*)&l2 | ((uint32_t)*(uint16_t*)&l3 << 16);
  *reinterpret_cast<uint2*>(yl + e) = make_uint2(q0, q1);
}

// ---------------------------------------------------------------------------
// Causal depthwise conv (K=4) + SiLU. Reads strided src, writes dense [M,1024].
// ---------------------------------------------------------------------------
__global__ void __launch_bounds__(256) conv_silu_kernel(
    const float* __restrict__ src, int ld, int colOff,
    const float* __restrict__ w, float* __restrict__ y) {
  int idx = blockIdx.x * 256 + threadIdx.x;
  if (idx >= ROWS * D_) return;
  int c = idx & 1023;
  int row = idx >> 10;
  int t = row & 1023;
  const float* sp = src + (size_t)row * ld + colOff + c;
  float acc = 0.f;
#pragma unroll
  for (int i = 0; i < 4; i++) {
    int tt = t + i - 3;
    if (tt >= 0) acc += sp[(i - 3) * ld] * w[c * 4 + i];
  }
  y[idx] = acc / (1.f + expf(-acc));
}

// ---------------------------------------------------------------------------
// Per-64 l2norm, warp/group, in place fp32.
// ---------------------------------------------------------------------------
__global__ void __launch_bounds__(256) norm64_l2_kernel(
    float* __restrict__ x, float scale, int ngroups) {
  int gw = (blockIdx.x * blockDim.x + threadIdx.x) >> 5;
  int lane = threadIdx.x & 31;
  if (gw >= ngroups) return;
  float* p = x + (size_t)gw * 64;
  float a = p[lane];
  float b = p[lane + 32];
  float ss = a * a + b * b;
#pragma unroll
  for (int o = 16; o > 0; o >>= 1) ss += __shfl_xor_sync(0xffffffffu, ss, o);
  float r = rsqrtf(ss + 1e-6f) * scale;
  p[lane] = a * r;
  p[lane + 32] = b * r;
}

// ---------------------------------------------------------------------------
// Per-64 RMSNorm -> blocked bf16 hi/lo (nK = 32).
// ---------------------------------------------------------------------------
__global__ void __launch_bounds__(256) norm64_rms_split_kernel(
    const float* __restrict__ x, const float* __restrict__ w,
    __nv_bfloat16* __restrict__ yh, __nv_bfloat16* __restrict__ yl,
    int ngroups) {
  int gw = (blockIdx.x * blockDim.x + threadIdx.x) >> 5;
  int lane = threadIdx.x & 31;
  if (gw >= ngroups) return;
  const float* p = x + (size_t)gw * 64;
  float a = p[lane];
  float b = p[lane + 32];
  float ss = a * a + b * b;
#pragma unroll
  for (int o = 16; o > 0; o >>= 1) ss += __shfl_xor_sync(0xffffffffu, ss, o);
  float r = rsqrtf(ss * (1.f / 64.f) + 1e-6f);
  a *= r * w[lane];
  b *= r * w[lane + 32];
  int row = gw >> 4;
  int k0 = (gw & 15) * 64;
  __nv_bfloat16 h, l;
  split1(a, h, l);
  size_t e = blk_off(row, k0 + lane, 32);
  yh[e] = h; yl[e] = l;
  split1(b, h, l);
  e = blk_off(row, k0 + lane + 32, 32);
  yh[e] = h; yl[e] = l;
}

// ---------------------------------------------------------------------------
// beta/g gates: block per row.
// ---------------------------------------------------------------------------
__global__ void __launch_bounds__(256) betag_kernel(
    const float* __restrict__ h, const float* __restrict__ Wb,
    const float* __restrict__ Wa, const float* __restrict__ dt_bias,
    const float* __restrict__ A_log, float* __restrict__ beta,
    float* __restrict__ gout) {
  __shared__ float hs[D_];
  __shared__ float pb[256], pa[256];
  int row = blockIdx.x;
  int tid = threadIdx.x;
  reinterpret_cast<float4*>(hs)[tid] =
      reinterpret_cast<const float4*>(h + (size_t)row * D_)[tid];
  __syncthreads();
  int head = tid & 15;
  int chunk = tid >> 4;
  float sb = 0.f, sa = 0.f;
  int base = chunk * 64;
#pragma unroll 8
  for (int i = 0; i < 64; i++) {
    float hv = hs[base + i];
    int wi = (base + i) * 16 + head;
    sb += hv * Wb[wi];
    sa += hv * Wa[wi];
  }
  pb[tid] = sb;
  pa[tid] = sa;
  __syncthreads();
  if (tid < 16) {
    float b = 0.f, a = 0.f;
#pragma unroll
    for (int c = 0; c < 16; c++) {
      b += pb[c * 16 + tid];
      a += pa[c * 16 + tid];
    }
    beta[row * H_ + tid] = 2.f / (1.f + expf(-b));
    float z = a + dt_bias[tid];
    float sp = (z > 20.f) ? z : log1pf(expf(z));
    gout[row * H_ + tid] = -expf(A_log[tid]) * sp;
  }
}

// ---------------------------------------------------------------------------
// Delta-rule scan: 128 blocks (2 per (b,h), 32 v-cols each), 128 threads.
// Restructured math: kv = eg*<k,s>, op = eg*<q,s> + delta*<q,k>.
// ---------------------------------------------------------------------------
__global__ void __launch_bounds__(128) scan_kernel(
    const float* __restrict__ q, const float* __restrict__ k,
    const float* __restrict__ v, const float* __restrict__ beta,
    const float* __restrict__ g, float* __restrict__ o,
    float* __restrict__ state_out) {
  int blk = blockIdx.x;
  int bh = blk >> 1;
  int half = blk & 1;
  int b = bh >> 4, h = bh & 15;
  int tid = threadIdx.x;
  int colL = tid >> 2;            // 0..31 local col
  int col = half * 32 + colL;
  int kq = tid & 3;

  __shared__ float qs[2][64], ks[2][64], vs[2][32], sc[2][2];
  float s[16];
#pragma unroll
  for (int i = 0; i < 16; i++) s[i] = 0.f;

  size_t vecbase = (size_t)b * T_ * 1024 + (size_t)h * 64;
  int bgbase = b * T_ * H_ + h;

  const float* src1 = (tid < 64) ? (q + vecbase + tid) : (k + vecbase + tid - 64);
  const float* src2 = nullptr;
  int str2 = 1024;
  if (tid < 32)        src2 = v + vecbase + half * 32 + tid;
  else if (tid == 32) { src2 = beta + bgbase; str2 = H_; }
  else if (tid == 33) { src2 = g + bgbase;    str2 = H_; }

  float p1 = src1[0];
  float p2 = (src2 != nullptr) ? src2[0] : 0.f;
  int buf = 0;

  for (int t = 0; t < T_; t++) {
    if (tid < 64) qs[buf][tid] = p1;
    else          ks[buf][tid - 64] = p1;
    if (tid < 32)       vs[buf][tid] = p2;
    else if (tid == 32) sc[buf][0] = p2;
    else if (tid == 33) sc[buf][1] = p2;
    __syncthreads();
    if (t + 1 < T_) {
      p1 = src1[(size_t)(t + 1) * 1024];
      if (src2 != nullptr) p2 = src2[(size_t)(t + 1) * str2];
    }

    float eg = expf(sc[buf][1]);
    float bt = sc[buf][0];
    float kk[16], qq[16];
#pragma unroll
    for (int i = 0; i < 16; i++) {
      kk[i] = ks[buf][kq * 16 + i];
      qq[i] = qs[buf][kq * 16 + i];
    }
    float kv0 = 0.f, kv1 = 0.f, qv0 = 0.f, qv1 = 0.f, qk0 = 0.f, qk1 = 0.f;
#pragma unroll
    for (int i = 0; i < 16; i += 2) {
      kv0 += kk[i] * s[i];     kv1 += kk[i + 1] * s[i + 1];
      qv0 += qq[i] * s[i];     qv1 += qq[i + 1] * s[i + 1];
      qk0 += qq[i] * kk[i];    qk1 += qq[i + 1] * kk[i + 1];
    }
    float kv = kv0 + kv1, qv = qv0 + qv1, qk = qk0 + qk1;
    kv += __shfl_xor_sync(0xffffffffu, kv, 1);
    kv += __shfl_xor_sync(0xffffffffu, kv, 2);
    qv += __shfl_xor_sync(0xffffffffu, qv, 1);
    qv += __shfl_xor_sync(0xffffffffu, qv, 2);
    qk += __shfl_xor_sync(0xffffffffu, qk, 1);
    qk += __shfl_xor_sync(0xffffffffu, qk, 2);

    float delta = (vs[buf][colL] - eg * kv) * bt;
#pragma unroll
    for (int i = 0; i < 16; i++) s[i] = eg * s[i] + kk[i] * delta;
    if (kq == 0) o[vecbase + (size_t)t * 1024 + col] = eg * qv + delta * qk;
    buf ^= 1;
  }

  float* sp = state_out + (size_t)bh * 64 * 64;
#pragma unroll
  for (int i = 0; i < 16; i++) sp[(kq * 16 + i) * 64 + col] = s[i];
}

// ---------------------------------------------------------------------------
// SwiGLU -> blocked bf16 hi/lo (K = 2816, nK = 88).
// ---------------------------------------------------------------------------
__global__ void __launch_bounds__(256) swiglu_split_kernel(
    const float* __restrict__ gy, __nv_bfloat16* __restrict__ uh,
    __nv_bfloat16* __restrict__ ul) {
  int idx4 = blockIdx.x * 256 + threadIdx.x;
  int total = ROWS * (I_ / 4);
  if (idx4 >= total) return;
  int row = idx4 / (I_ / 4);
  int c0 = (idx4 - row * (I_ / 4)) * 4;
  float4 gv = *reinterpret_cast<const float4*>(gy + (size_t)row * TWOI + c0);
  float4 yv = *reinterpret_cast<const float4*>(gy + (size_t)row * TWOI + I_ + c0);
  float u0 = gv.x / (1.f + expf(-gv.x)) * yv.x;
  float u1 = gv.y / (1.f + expf(-gv.y)) * yv.y;
  float u2 = gv.z / (1.f + expf(-gv.z)) * yv.z;
  float u3 = gv.w / (1.f + expf(-gv.w)) * yv.w;
  __nv_bfloat16 h0, h1, h2, h3, l0, l1, l2, l3;
  split1(u0, h0, l0); split1(u1, h1, l1);
  split1(u2, h2, l2); split1(u3, h3, l3);
  size_t e = blk_off(row, c0, 88);
  uint32_t p0 = (uint32_t)*(uint16_t*)&h0 | ((uint32_t)*(uint16_t*)&h1 << 16);
  uint32_t p1 = (uint32_t)*(uint16_t*)&h2 | ((uint32_t)*(uint16_t*)&h3 << 16);
  *reinterpret_cast<uint2*>(uh + e) = make_uint2(p0, p1);
  uint32_t q0 = (uint32_t)*(uint16_t*)&l0 | ((uint32_t)*(uint16_t*)&l1 << 16);
  uint32_t q1 = (uint32_t)*(uint16_t*)&l2 | ((uint32_t)*(uint16_t*)&l3 << 16);
  *reinterpret_cast<uint2*>(ul + e) = make_uint2(q0, q1);
}

// ---------------------------------------------------------------------------
extern "C" void kernel_launch(void* const* d_in, const int* in_sizes, int n_in,
                              void* d_out, int out_size) {
  const float* x           = (const float*)d_in[0];
  const float* attn_norm_w = (const float*)d_in[1];
  const float* Wq          = (const float*)d_in[2];
  const float* Wk          = (const float*)d_in[3];
  const float* Wv          = (const float*)d_in[4];
  const float* conv_q_w    = (const float*)d_in[5];
  const float* conv_k_w    = (const float*)d_in[6];
  const float* conv_v_w    = (const float*)d_in[7];
  const float* Wb          = (const float*)d_in[8];
  const float* Wa          = (const float*)d_in[9];
  const float* dt_bias     = (const float*)d_in[10];
  const float* A_log       = (const float*)d_in[11];
  const float* o_norm_w    = (const float*)d_in[12];
  const float* Wo          = (const float*)d_in[13];
  const float* mlp_norm_w  = (const float*)d_in[14];
  const float* Wg          = (const float*)d_in[15];
  const float* Wd          = (const float*)d_in[16];
  float* out = (float*)d_out;

  float* pool = nullptr;
  cudaGetSymbolAddress((void**)&pool, g_pool);
  __nv_bfloat16* bf = nullptr;
  cudaGetSymbolAddress((void**)&bf, g_bf);

  cudaFuncSetAttribute(bf16gemm_kernel,
                       cudaFuncAttributeMaxDynamicSharedMemorySize, GEMM_SMEM);

  float* hbuf = pool + OFF_H;
  float* qkvp = pool + OFF_QKV;
  float* qbuf = pool + OFF_Q;
  float* kbuf = pool + OFF_K;
  float* vbuf = pool + OFF_V;
  float* obuf = pool + OFF_O;
  float* h2   = pool + OFF_H2;
  float* gy   = pool + OFF_GY;
  float* bbuf = pool + OFF_BETA;
  float* gbuf = pool + OFF_G;

  dim3 gW(D_ / 32, D_ / 32);  // (32, 32)

  // 0: h = rmsnorm(x) -> fp32 + blocked hi/lo
  rmsnorm_split_kernel<<<ROWS, 256>>>(x, attn_norm_w, hbuf,
                                      bf + BF_AH, bf + BF_AL);
  // 1-3: Wq/Wk/Wv split (QKV weight n-tiles 0-7 / 8-15 / 16-23)
  wsplit_kernel<<<gW, 256>>>(Wq, bf + BF_WQKVH, bf + BF_WQKVL, D_, D_, 32);
  wsplit_kernel<<<gW, 256>>>(Wk, bf + BF_WQKVH + W1, bf + BF_WQKVL + W1, D_, D_, 32);
  wsplit_kernel<<<gW, 256>>>(Wv, bf + BF_WQKVH + 2 * W1, bf + BF_WQKVL + 2 * W1, D_, D_, 32);

  // 4: fused QKV GEMM (profiled launch)
  bf16gemm_kernel<<<dim3(24, 16), 256, GEMM_SMEM>>>(
      bf + BF_AH, bf + BF_AL, bf + BF_WQKVH, bf + BF_WQKVL,
      nullptr, qkvp, 3072, 32);

  // other weight splits
  wsplit_kernel<<<gW, 256>>>(Wo, bf + BF_WOH, bf + BF_WOL, D_, D_, 32);
  wsplit_kernel<<<dim3(TWOI / 32, D_ / 32), 256>>>(Wg, bf + BF_WGH, bf + BF_WGL, D_, TWOI, 32);
  wsplit_kernel<<<dim3(D_ / 32, I_ / 32), 256>>>(Wd, bf + BF_WDH, bf + BF_WDL, I_, D_, 88);

  // gates
  betag_kernel<<<ROWS, 256>>>(hbuf, Wb, Wa, dt_bias, A_log, bbuf, gbuf);

  // conv + SiLU (read fused qkv, ld=3072)
  int nel = ROWS * D_;
  conv_silu_kernel<<<nel / 256, 256>>>(qkvp, 3072, 0, conv_q_w, qbuf);
  conv_silu_kernel<<<nel / 256, 256>>>(qkvp, 3072, 1024, conv_k_w, kbuf);
  conv_silu_kernel<<<nel / 256, 256>>>(qkvp, 3072, 2048, conv_v_w, vbuf);

  // l2norm
  int ngrp = ROWS * H_;
  int nblk64 = (ngrp * 32) / 256;
  norm64_l2_kernel<<<nblk64, 256>>>(qbuf, 0.125f, ngrp);
  norm64_l2_kernel<<<nblk64, 256>>>(kbuf, 1.0f, ngrp);

  // scan (128 blocks)
  scan_kernel<<<128, 128>>>(qbuf, kbuf, vbuf, bbuf, gbuf, obuf, out + SZ);

  // per-head RMSNorm -> blocked hi/lo
  norm64_rms_split_kernel<<<nblk64, 256>>>(obuf, o_norm_w,
                                           bf + BF_OH, bf + BF_OL, ngrp);

  // h2 = o @ Wo + x
  bf16gemm_kernel<<<dim3(8, 16), 256, GEMM_SMEM>>>(
      bf + BF_OH, bf + BF_OL, bf + BF_WOH, bf + BF_WOL, x, h2, 1024, 32);

  // h3 = rmsnorm(h2) -> blocked hi/lo
  rmsnorm_split_kernel<<<ROWS, 256>>>(h2, mlp_norm_w, nullptr,
                                      bf + BF_3H, bf + BF_3L);

  // gy = h3 @ Wg
  bf16gemm_kernel<<<dim3(44, 16), 256, GEMM_SMEM>>>(
      bf + BF_3H, bf + BF_3L, bf + BF_WGH, bf + BF_WGL, nullptr, gy, TWOI, 32);

  // SwiGLU -> blocked hi/lo
  swiglu_split_kernel<<<(ROWS * (I_ / 4) + 255) / 256, 256>>>(
      gy, bf + BF_UH, bf + BF_UL);

  // out = u @ Wd + h2
  bf16gemm_kernel<<<dim3(8, 16), 256, GEMM_SMEM>>>(
      bf + BF_UH, bf + BF_UL, bf + BF_WDH, bf + BF_WDL, h2, out, 1024, 88);
}